// round 4
// baseline (speedup 1.0000x reference)
#include <cuda_runtime.h>
#include <cuda_bf16.h>
#include <math.h>
#include <stdint.h>

#define FULL 0xffffffffu

__device__ float g_tn[32 * 128];

__device__ __forceinline__ float gelu_exact(float z) {
    return 0.5f * z * (1.0f + erff(z * 0.70710678118654752f));
}

// pack value as (bf16_hi | bf16_lo<<16); hi+lo == v to ~2^-16 rel
__device__ __forceinline__ uint32_t pack_hl(float v) {
    __nv_bfloat16 h = __float2bfloat16(v);
    float hf = __bfloat162float(h);
    __nv_bfloat16 l = __float2bfloat16(v - hf);
    return (uint32_t)__bfloat16_as_ushort(h)
         | ((uint32_t)__bfloat16_as_ushort(l) << 16);
}

__device__ __forceinline__ void mma_bf16(float* c, const uint32_t* a,
                                         uint32_t b0, uint32_t b1) {
    asm volatile(
        "mma.sync.aligned.m16n8k16.row.col.f32.bf16.bf16.f32 "
        "{%0,%1,%2,%3}, {%4,%5,%6,%7}, {%8,%9}, {%0,%1,%2,%3};\n"
        : "+f"(c[0]), "+f"(c[1]), "+f"(c[2]), "+f"(c[3])
        : "r"(a[0]), "r"(a[1]), "r"(a[2]), "r"(a[3]), "r"(b0), "r"(b1));
}

// ---------------------------------------------------------------------------
// Kernel 1: token path (unchanged).
// ---------------------------------------------------------------------------
__global__ void token_kernel(const float* __restrict__ token,
                             const float* __restrict__ ln1_g,
                             const float* __restrict__ ln1_b,
                             const float* __restrict__ w_tok,
                             const float* __restrict__ b_tok)
{
    __shared__ float st[768];
    __shared__ float spart[256];
    __shared__ float sy[128];
    __shared__ float sred[8];
    __shared__ float sredq[8];

    const int b = blockIdx.x;
    const int tid = threadIdx.x;
    const int wid = tid >> 5, lane = tid & 31;
    const float* trow = token + b * 768;

    float s = 0.f, sq = 0.f;
    for (int i = tid; i < 768; i += 256) {
        float v = trow[i];
        st[i] = v;
        s += v; sq += v * v;
    }
    #pragma unroll
    for (int o = 16; o; o >>= 1) {
        s  += __shfl_down_sync(FULL, s,  o);
        sq += __shfl_down_sync(FULL, sq, o);
    }
    if (lane == 0) { sred[wid] = s; sredq[wid] = sq; }
    __syncthreads();
    if (tid == 0) {
        float ts = 0.f, tq = 0.f;
        #pragma unroll
        for (int i = 0; i < 8; i++) { ts += sred[i]; tq += sredq[i]; }
        sred[0] = ts; sredq[0] = tq;
    }
    __syncthreads();
    const float mean = sred[0] * (1.0f / 768.0f);
    const float var  = sredq[0] * (1.0f / 768.0f) - mean * mean;
    const float rstd = rsqrtf(var + 1e-6f);
    __syncthreads();

    for (int i = tid; i < 768; i += 256)
        st[i] = (st[i] - mean) * rstd * ln1_g[i] + ln1_b[i];
    __syncthreads();

    const int n = tid & 127, half = tid >> 7;
    const int k0 = half * 384;
    const float* wp = w_tok + n;
    float acc = 0.f;
    #pragma unroll 8
    for (int k = 0; k < 384; k++)
        acc += st[k0 + k] * wp[(size_t)(k0 + k) * 128];
    spart[tid] = acc;
    __syncthreads();

    if (tid < 128) {
        float z = spart[tid] + spart[tid + 128] + b_tok[tid];
        sy[tid] = gelu_exact(z);
    }
    __syncthreads();

    float q = 0.f;
    if (tid < 128) { float v = sy[tid]; q = v * v; }
    #pragma unroll
    for (int o = 16; o; o >>= 1) q += __shfl_down_sync(FULL, q, o);
    if (lane == 0) sred[wid] = q;
    __syncthreads();
    if (tid == 0) {
        float t = 0.f;
        #pragma unroll
        for (int i = 0; i < 8; i++) t += sred[i];
        sred[0] = t;
    }
    __syncthreads();
    if (tid < 128) {
        float nrm = sqrtf(sred[0]);
        g_tn[b * 128 + tid] = sy[tid] / fmaxf(nrm, 1e-12f);
    }
}

// ---------------------------------------------------------------------------
// Kernel 2: persistent fused main path. 1 CTA/SM, 256 thr, 215.5KB smem.
// Tiles of 128 rows; GEMM 128x128x192 via bf16 hi/lo 3-term m16n8k16.
// Warp tile 64 rows x 32 cols (rowg = wid&1, colg = wid>>1).
// ---------------------------------------------------------------------------
#define APAD 200
#define NTILES 1024
// mf word offsets
#define MI_SMEAN 0
#define MI_SVAR  256
#define MI_SC    512
#define MI_SDOT  640
#define MI_SSQ   1152
#define MI_STN   1664
#define MI_SBX   1792
#define MI_SG2   1920
#define MI_SB2   2112
#define MI_SG3   2304
#define MI_SB3   2496
#define MF_WORDS 2688
#define SMEM_WORDS (128 * APAD + 128 * APAD + MF_WORDS)

__global__ void __launch_bounds__(256, 1) main_kernel(
    const float* __restrict__ x,
    const float* __restrict__ p,
    const float* __restrict__ alpha,
    const float* __restrict__ ln2_g, const float* __restrict__ ln2_b,
    const float* __restrict__ w_x,  const float* __restrict__ b_x,
    const float* __restrict__ ln3_g, const float* __restrict__ ln3_b,
    float* __restrict__ out)
{
    extern __shared__ float sm[];
    uint32_t* Asu = (uint32_t*)sm;            // [128][APAD] packed hi/lo
    uint32_t* Bsu = Asu + 128 * APAD;         // [128 n][APAD k] packed hi/lo
    float* mf = (float*)(Bsu + 128 * APAD);

    const int tid = threadIdx.x;
    const int wid = tid >> 5, lane = tid & 31;
    const int g = lane >> 2, t4 = lane & 3;

    // ---- persistent setup: misc params + B staged once ----
    if (tid < 128) mf[MI_SBX + tid] = b_x[tid];
    if (tid < 192) {
        mf[MI_SG2 + tid] = ln2_g[tid]; mf[MI_SB2 + tid] = ln2_b[tid];
        mf[MI_SG3 + tid] = ln3_g[tid]; mf[MI_SB3 + tid] = ln3_b[tid];
    }
    {   // B[n][k] = w_x[k][n], packed hi/lo
        const float4* w4 = (const float4*)w_x;
        for (int i = tid; i < 192 * 32; i += 256) {
            const int k = i >> 5, n0 = (i & 31) * 4;
            float4 v = w4[i];
            Bsu[(n0 + 0) * APAD + k] = pack_hl(v.x);
            Bsu[(n0 + 1) * APAD + k] = pack_hl(v.y);
            Bsu[(n0 + 2) * APAD + k] = pack_hl(v.z);
            Bsu[(n0 + 3) * APAD + k] = pack_hl(v.w);
        }
    }

    const int rowg = wid & 1, colg = wid >> 1;

    int it = 0;
    for (int tile = blockIdx.x; tile < NTILES; tile += gridDim.x, it++) {
        const int db = (it & 1) * 128;
        const int b = tile >> 5;
        const size_t base = (size_t)tile * 128 * 192;
        const float* xb = x + base;
        float* ob = out + base;

        if (tid < 128) mf[MI_STN + tid] = g_tn[b * 128 + tid];

        // ---- Phase 1: LN2 + hi/lo pack into As ----
        for (int rr = 0; rr < 16; rr++) {
            const int r = wid * 16 + rr;
            const float2* xr = (const float2*)(xb + r * 192);
            float2 v[3];
            float s = 0.f, sq = 0.f;
            #pragma unroll
            for (int j = 0; j < 3; j++) {
                v[j] = xr[lane + 32 * j];
                s += v[j].x + v[j].y;
                sq += v[j].x * v[j].x + v[j].y * v[j].y;
            }
            #pragma unroll
            for (int o = 16; o; o >>= 1) {
                s  += __shfl_down_sync(FULL, s,  o);
                sq += __shfl_down_sync(FULL, sq, o);
            }
            s  = __shfl_sync(FULL, s, 0);
            sq = __shfl_sync(FULL, sq, 0);
            const float mean = s * (1.0f / 192.0f);
            const float var  = sq * (1.0f / 192.0f) - mean * mean;
            const float rstd = rsqrtf(var + 1e-6f);
            if (lane == 0) { mf[MI_SMEAN + db + r] = mean; mf[MI_SVAR + db + r] = var; }
            #pragma unroll
            for (int j = 0; j < 3; j++) {
                const int c = 2 * lane + 64 * j;
                uint2 w;
                w.x = pack_hl((v[j].x - mean) * rstd * mf[MI_SG2 + c]     + mf[MI_SB2 + c]);
                w.y = pack_hl((v[j].y - mean) * rstd * mf[MI_SG2 + c + 1] + mf[MI_SB2 + c + 1]);
                *(uint2*)&Asu[r * APAD + c] = w;
            }
        }
        __syncthreads();

        // ---- Phase 2: GEMM, warp tile 64x32, 12 k16-steps, 3 terms ----
        float acc[4][4][4];
        #pragma unroll
        for (int mt = 0; mt < 4; mt++)
            #pragma unroll
            for (int nt = 0; nt < 4; nt++)
                #pragma unroll
                for (int i = 0; i < 4; i++) acc[mt][nt][i] = 0.f;

        #pragma unroll
        for (int ks = 0; ks < 12; ks++) {
            const int k0 = ks * 16 + 2 * t4;
            uint32_t ah[4][4], al[4][4];
            #pragma unroll
            for (int mt = 0; mt < 4; mt++) {
                const uint32_t* A0 = &Asu[(rowg * 64 + mt * 16 + g) * APAD + k0];
                const uint2 p0 = *(const uint2*)A0;
                const uint2 p1 = *(const uint2*)(A0 + 8 * APAD);
                const uint2 p2 = *(const uint2*)(A0 + 8);
                const uint2 p3 = *(const uint2*)(A0 + 8 * APAD + 8);
                ah[mt][0] = __byte_perm(p0.x, p0.y, 0x5410);
                al[mt][0] = __byte_perm(p0.x, p0.y, 0x7632);
                ah[mt][1] = __byte_perm(p1.x, p1.y, 0x5410);
                al[mt][1] = __byte_perm(p1.x, p1.y, 0x7632);
                ah[mt][2] = __byte_perm(p2.x, p2.y, 0x5410);
                al[mt][2] = __byte_perm(p2.x, p2.y, 0x7632);
                ah[mt][3] = __byte_perm(p3.x, p3.y, 0x5410);
                al[mt][3] = __byte_perm(p3.x, p3.y, 0x7632);
            }
            uint32_t bh[4][2], bl[4][2];
            #pragma unroll
            for (int nt = 0; nt < 4; nt++) {
                const uint32_t* B0 = &Bsu[(colg * 32 + nt * 8 + g) * APAD + k0];
                const uint2 q0 = *(const uint2*)B0;
                const uint2 q1 = *(const uint2*)(B0 + 8);
                bh[nt][0] = __byte_perm(q0.x, q0.y, 0x5410);
                bl[nt][0] = __byte_perm(q0.x, q0.y, 0x7632);
                bh[nt][1] = __byte_perm(q1.x, q1.y, 0x5410);
                bl[nt][1] = __byte_perm(q1.x, q1.y, 0x7632);
            }
            #pragma unroll
            for (int mt = 0; mt < 4; mt++)
                #pragma unroll
                for (int nt = 0; nt < 4; nt++) {
                    mma_bf16(acc[mt][nt], ah[mt], bh[nt][0], bh[nt][1]);
                    mma_bf16(acc[mt][nt], ah[mt], bl[nt][0], bl[nt][1]);
                    mma_bf16(acc[mt][nt], al[mt], bh[nt][0], bh[nt][1]);
                }
        }

        // ---- Epilogue: gelu, dot with tn, sumsq; partials per colg ----
        #pragma unroll
        for (int mt = 0; mt < 4; mt++) {
            #pragma unroll
            for (int h = 0; h < 2; h++) {
                float dot = 0.f, ssq = 0.f;
                #pragma unroll
                for (int nt = 0; nt < 4; nt++) {
                    #pragma unroll
                    for (int c2 = 0; c2 < 2; c2++) {
                        const int col = colg * 32 + nt * 8 + t4 * 2 + c2;
                        const float z = acc[mt][nt][h * 2 + c2] + mf[MI_SBX + col];
                        const float e = gelu_exact(z);
                        dot += e * mf[MI_STN + col];
                        ssq += e * e;
                    }
                }
                dot += __shfl_xor_sync(FULL, dot, 1);
                dot += __shfl_xor_sync(FULL, dot, 2);
                ssq += __shfl_xor_sync(FULL, ssq, 1);
                ssq += __shfl_xor_sync(FULL, ssq, 2);
                if (t4 == 0) {
                    const int row = rowg * 64 + mt * 16 + g + h * 8;
                    mf[MI_SDOT + colg * 128 + row] = dot;
                    mf[MI_SSQ  + colg * 128 + row] = ssq;
                }
            }
        }
        __syncthreads();

        if (tid < 128) {
            const float dot = mf[MI_SDOT + tid] + mf[MI_SDOT + 128 + tid]
                            + mf[MI_SDOT + 256 + tid] + mf[MI_SDOT + 384 + tid];
            const float ssq = mf[MI_SSQ + tid] + mf[MI_SSQ + 128 + tid]
                            + mf[MI_SSQ + 256 + tid] + mf[MI_SSQ + 384 + tid];
            const float ps = p[b] * expf(alpha[0]);
            const float a  = ps * dot / fmaxf(sqrtf(ssq), 1e-12f);
            // LN3(a*x) = (x - m) * a * rsqrt(a^2 v + eps) * g3 + b3
            mf[MI_SC + tid] = a * rsqrtf(a * a * mf[MI_SVAR + db + tid] + 1e-6f);
        }
        __syncthreads();

        // ---- Phase 3: residual write (no barrier after; overlaps next P1) ----
        {
            const float4* xb4 = (const float4*)xb;
            float4* ob4 = (float4*)ob;
            #pragma unroll
            for (int i = tid; i < 128 * 48; i += 256) {
                const int r = i / 48;
                const int c = (i - r * 48) * 4;
                const float4 xv = xb4[i];
                const float m = mf[MI_SMEAN + db + r], scv = mf[MI_SC + r];
                float4 o;
                o.x = 0.5f * xv.x + (xv.x - m) * scv * mf[MI_SG3 + c]     + mf[MI_SB3 + c];
                o.y = 0.5f * xv.y + (xv.y - m) * scv * mf[MI_SG3 + c + 1] + mf[MI_SB3 + c + 1];
                o.z = 0.5f * xv.z + (xv.z - m) * scv * mf[MI_SG3 + c + 2] + mf[MI_SB3 + c + 2];
                o.w = 0.5f * xv.w + (xv.w - m) * scv * mf[MI_SG3 + c + 3] + mf[MI_SB3 + c + 3];
                ob4[i] = o;
            }
        }
    }
}

// ---------------------------------------------------------------------------
extern "C" void kernel_launch(void* const* d_in, const int* in_sizes, int n_in,
                              void* d_out, int out_size)
{
    (void)in_sizes; (void)n_in; (void)out_size;
    const float* x     = (const float*)d_in[0];
    const float* token = (const float*)d_in[1];
    const float* p     = (const float*)d_in[2];
    const float* alpha = (const float*)d_in[3];
    const float* ln1_g = (const float*)d_in[4];
    const float* ln1_b = (const float*)d_in[5];
    const float* w_tok = (const float*)d_in[6];
    const float* b_tok = (const float*)d_in[7];
    const float* ln2_g = (const float*)d_in[8];
    const float* ln2_b = (const float*)d_in[9];
    const float* w_x   = (const float*)d_in[10];
    const float* b_x   = (const float*)d_in[11];
    const float* ln3_g = (const float*)d_in[12];
    const float* ln3_b = (const float*)d_in[13];
    float* out = (float*)d_out;

    token_kernel<<<32, 256>>>(token, ln1_g, ln1_b, w_tok, b_tok);

    static int nsm = 0;
    if (nsm == 0) {
        cudaDeviceGetAttribute(&nsm, cudaDevAttrMultiProcessorCount, 0);
        if (nsm <= 0) nsm = 148;
    }
    const size_t smem = SMEM_WORDS * sizeof(float);
    cudaFuncSetAttribute(main_kernel, cudaFuncAttributeMaxDynamicSharedMemorySize,
                         (int)smem);
    main_kernel<<<nsm, 256, smem>>>(x, p, alpha, ln2_g, ln2_b, w_x, b_x,
                                    ln3_g, ln3_b, out);
}

// round 5
// speedup vs baseline: 1.5345x; 1.5345x over previous
#include <cuda_runtime.h>
#include <cuda_bf16.h>
#include <math.h>
#include <stdint.h>

#define FULL 0xffffffffu

__device__ float g_tn[32 * 128];
__device__ float g_y[32 * 128];

__device__ __forceinline__ float gelu_exact(float z) {
    return 0.5f * z * (1.0f + erff(z * 0.70710678118654752f));
}

// pack value as (bf16_hi | bf16_lo<<16); hi+lo == v to ~2^-16 rel
__device__ __forceinline__ uint32_t pack_hl(float v) {
    __nv_bfloat16 h = __float2bfloat16(v);
    float hf = __bfloat162float(h);
    __nv_bfloat16 l = __float2bfloat16(v - hf);
    return (uint32_t)__bfloat16_as_ushort(h)
         | ((uint32_t)__bfloat16_as_ushort(l) << 16);
}

__device__ __forceinline__ void mma_bf16(float* c, const uint32_t* a,
                                         uint32_t b0, uint32_t b1) {
    asm volatile(
        "mma.sync.aligned.m16n8k16.row.col.f32.bf16.bf16.f32 "
        "{%0,%1,%2,%3}, {%4,%5,%6,%7}, {%8,%9}, {%0,%1,%2,%3};\n"
        : "+f"(c[0]), "+f"(c[1]), "+f"(c[2]), "+f"(c[3])
        : "r"(a[0]), "r"(a[1]), "r"(a[2]), "r"(a[3]), "r"(b0), "r"(b1));
}

// ---------------------------------------------------------------------------
// Kernel 1a: token projection.  Grid (4, 32): x=col-quarter, y=batch. 256 thr.
// g_y[b][n] = gelu(LN1(token[b]) @ w_tok[:,n] + b_tok[n])
// ---------------------------------------------------------------------------
__global__ void token_proj(const float* __restrict__ token,
                           const float* __restrict__ ln1_g,
                           const float* __restrict__ ln1_b,
                           const float* __restrict__ w_tok,
                           const float* __restrict__ b_tok)
{
    __shared__ float st[768];
    __shared__ float sred[8];
    __shared__ float sredq[8];
    __shared__ float spart[8][32];

    const int b = blockIdx.y, nq = blockIdx.x;
    const int tid = threadIdx.x;
    const int wid = tid >> 5, lane = tid & 31;
    const float* trow = token + b * 768;

    float s = 0.f, sq = 0.f;
    for (int i = tid; i < 768; i += 256) {
        float v = trow[i];
        st[i] = v;
        s += v; sq += v * v;
    }
    #pragma unroll
    for (int o = 16; o; o >>= 1) {
        s  += __shfl_down_sync(FULL, s,  o);
        sq += __shfl_down_sync(FULL, sq, o);
    }
    if (lane == 0) { sred[wid] = s; sredq[wid] = sq; }
    __syncthreads();
    if (tid == 0) {
        float ts = 0.f, tq = 0.f;
        #pragma unroll
        for (int i = 0; i < 8; i++) { ts += sred[i]; tq += sredq[i]; }
        sred[0] = ts; sredq[0] = tq;
    }
    __syncthreads();
    const float mean = sred[0] * (1.0f / 768.0f);
    const float var  = sredq[0] * (1.0f / 768.0f) - mean * mean;
    const float rstd = rsqrtf(var + 1e-6f);
    __syncthreads();
    for (int i = tid; i < 768; i += 256)
        st[i] = (st[i] - mean) * rstd * ln1_g[i] + ln1_b[i];
    __syncthreads();

    // GEMV for 32 columns: 256 threads = 32 cols x 8 k-slices of 96
    const int col = nq * 32 + (tid & 31);
    const int ks = tid >> 5;
    float acc = 0.f;
    const float* wp = w_tok + (size_t)ks * 96 * 128 + col;
    const float* sp = st + ks * 96;
    #pragma unroll 8
    for (int kk = 0; kk < 96; kk++)
        acc += sp[kk] * wp[(size_t)kk * 128];
    spart[ks][tid & 31] = acc;
    __syncthreads();

    if (tid < 32) {
        float z = b_tok[nq * 32 + tid];
        #pragma unroll
        for (int i = 0; i < 8; i++) z += spart[i][tid];
        g_y[b * 128 + nq * 32 + tid] = gelu_exact(z);
    }
}

// Kernel 1b: l2-normalize rows of g_y -> g_tn.  Grid 32, 128 thr.
__global__ void token_norm()
{
    __shared__ float red[4];
    const int b = blockIdx.x, tid = threadIdx.x;
    const int wid = tid >> 5, lane = tid & 31;
    const float v = g_y[b * 128 + tid];
    float q = v * v;
    #pragma unroll
    for (int o = 16; o; o >>= 1) q += __shfl_down_sync(FULL, q, o);
    if (lane == 0) red[wid] = q;
    __syncthreads();
    const float tot = red[0] + red[1] + red[2] + red[3];
    g_tn[b * 128 + tid] = v / fmaxf(sqrtf(tot), 1e-12f);
}

// ---------------------------------------------------------------------------
// Kernel 2: persistent fused main path. 512 thr (16 warps), 1 CTA/SM.
// 64-row tiles (2048 tiles), double-buffered A, register prefetch of next x.
// GEMM 64x128x192 bf16 hi/lo 3-term; warp tile 32x16 (rowg=wid&1, colg=wid>>1).
// ---------------------------------------------------------------------------
#define APAD 200
#define NTILES 2048
#define MI_SMEAN 0
#define MI_SVAR  128
#define MI_SC    256
#define MI_SDOT  320
#define MI_SSQ   832
#define MI_STN   1344
#define MI_SBX   1472
#define MI_SG2   1600
#define MI_SB2   1792
#define MI_SG3   1984
#define MI_SB3   2176
#define MF_WORDS 2368
#define SMEM_WORDS (2 * 64 * APAD + 128 * APAD + MF_WORDS)

__global__ void __launch_bounds__(512, 1) main_kernel(
    const float* __restrict__ x,
    const float* __restrict__ p,
    const float* __restrict__ alpha,
    const float* __restrict__ ln2_g, const float* __restrict__ ln2_b,
    const float* __restrict__ w_x,  const float* __restrict__ b_x,
    const float* __restrict__ ln3_g, const float* __restrict__ ln3_b,
    float* __restrict__ out)
{
    extern __shared__ float sm[];
    uint32_t* Asu = (uint32_t*)sm;            // [2][64][APAD] packed hi/lo
    uint32_t* Bsu = Asu + 2 * 64 * APAD;      // [128 n][APAD k] packed hi/lo
    float* mf = (float*)(Bsu + 128 * APAD);

    const int tid = threadIdx.x;
    const int wid = tid >> 5, lane = tid & 31;
    const int g = lane >> 2, t4 = lane & 3;
    const int rowg = wid & 1, colg = wid >> 1;

    // ---- persistent setup ----
    if (tid < 128) mf[MI_SBX + tid] = b_x[tid];
    if (tid < 192) {
        mf[MI_SG2 + tid] = ln2_g[tid]; mf[MI_SB2 + tid] = ln2_b[tid];
        mf[MI_SG3 + tid] = ln3_g[tid]; mf[MI_SB3 + tid] = ln3_b[tid];
    }
    {   // B[n][k] = w_x[k][n]; lanes iterate k -> conflict-free STS
        const float4* w4 = (const float4*)w_x;
        #pragma unroll
        for (int nn = wid; nn < 32; nn += 16) {
            for (int k = lane; k < 192; k += 32) {
                float4 v = w4[(size_t)k * 32 + nn];
                Bsu[(nn * 4 + 0) * APAD + k] = pack_hl(v.x);
                Bsu[(nn * 4 + 1) * APAD + k] = pack_hl(v.y);
                Bsu[(nn * 4 + 2) * APAD + k] = pack_hl(v.z);
                Bsu[(nn * 4 + 3) * APAD + k] = pack_hl(v.w);
            }
        }
    }

    // ---- prologue prefetch of first tile ----
    float2 v[4][3];
    {
        const float2* xr = (const float2*)(x + ((size_t)blockIdx.x * 64 + wid * 4) * 192);
        #pragma unroll
        for (int rr = 0; rr < 4; rr++)
            #pragma unroll
            for (int j = 0; j < 3; j++)
                v[rr][j] = xr[rr * 96 + lane + 32 * j];
    }

    int it = 0;
    for (int tile = blockIdx.x; tile < NTILES; tile += gridDim.x, it++) {
        const int db = (it & 1) * 64;
        const int Abase = (it & 1) * 64 * APAD;
        const int b = tile >> 6;
        const size_t base = (size_t)tile * 64 * 192;

        if (tid < 128) mf[MI_STN + tid] = g_tn[b * 128 + tid];

        // ---- Phase 1: LN2 + hi/lo pack from registers into As ----
        #pragma unroll
        for (int rr = 0; rr < 4; rr++) {
            const int r = wid * 4 + rr;
            float s = 0.f, sq = 0.f;
            #pragma unroll
            for (int j = 0; j < 3; j++) {
                s += v[rr][j].x + v[rr][j].y;
                sq += v[rr][j].x * v[rr][j].x + v[rr][j].y * v[rr][j].y;
            }
            #pragma unroll
            for (int o = 16; o; o >>= 1) {
                s  += __shfl_down_sync(FULL, s,  o);
                sq += __shfl_down_sync(FULL, sq, o);
            }
            s  = __shfl_sync(FULL, s, 0);
            sq = __shfl_sync(FULL, sq, 0);
            const float mean = s * (1.0f / 192.0f);
            const float var  = sq * (1.0f / 192.0f) - mean * mean;
            const float rstd = rsqrtf(var + 1e-6f);
            if (lane == 0) { mf[MI_SMEAN + db + r] = mean; mf[MI_SVAR + db + r] = var; }
            #pragma unroll
            for (int j = 0; j < 3; j++) {
                const int c = 2 * lane + 64 * j;
                uint2 w;
                w.x = pack_hl((v[rr][j].x - mean) * rstd * mf[MI_SG2 + c]     + mf[MI_SB2 + c]);
                w.y = pack_hl((v[rr][j].y - mean) * rstd * mf[MI_SG2 + c + 1] + mf[MI_SB2 + c + 1]);
                *(uint2*)&Asu[Abase + r * APAD + c] = w;
            }
        }
        __syncthreads();

        // ---- prefetch next tile's x into registers (covered by GEMM) ----
        {
            int nxt = tile + gridDim.x;
            if (nxt >= NTILES) nxt = tile;
            const float2* xr = (const float2*)(x + ((size_t)nxt * 64 + wid * 4) * 192);
            #pragma unroll
            for (int rr = 0; rr < 4; rr++)
                #pragma unroll
                for (int j = 0; j < 3; j++)
                    v[rr][j] = xr[rr * 96 + lane + 32 * j];
        }

        // ---- Phase 2: GEMM warp tile 32x16, 12 k16-steps, 3 terms ----
        float acc[2][2][4];
        #pragma unroll
        for (int mt = 0; mt < 2; mt++)
            #pragma unroll
            for (int nt = 0; nt < 2; nt++)
                #pragma unroll
                for (int i = 0; i < 4; i++) acc[mt][nt][i] = 0.f;

        #pragma unroll
        for (int ks = 0; ks < 12; ks++) {
            const int k0 = ks * 16 + 2 * t4;
            uint32_t ah[2][4], al[2][4];
            #pragma unroll
            for (int mt = 0; mt < 2; mt++) {
                const uint32_t* A0 = &Asu[Abase + (rowg * 32 + mt * 16 + g) * APAD + k0];
                const uint2 p0 = *(const uint2*)A0;
                const uint2 p1 = *(const uint2*)(A0 + 8 * APAD);
                const uint2 p2 = *(const uint2*)(A0 + 8);
                const uint2 p3 = *(const uint2*)(A0 + 8 * APAD + 8);
                ah[mt][0] = __byte_perm(p0.x, p0.y, 0x5410);
                al[mt][0] = __byte_perm(p0.x, p0.y, 0x7632);
                ah[mt][1] = __byte_perm(p1.x, p1.y, 0x5410);
                al[mt][1] = __byte_perm(p1.x, p1.y, 0x7632);
                ah[mt][2] = __byte_perm(p2.x, p2.y, 0x5410);
                al[mt][2] = __byte_perm(p2.x, p2.y, 0x7632);
                ah[mt][3] = __byte_perm(p3.x, p3.y, 0x5410);
                al[mt][3] = __byte_perm(p3.x, p3.y, 0x7632);
            }
            uint32_t bh[2][2], bl[2][2];
            #pragma unroll
            for (int nt = 0; nt < 2; nt++) {
                const uint32_t* B0 = &Bsu[(colg * 16 + nt * 8 + g) * APAD + k0];
                const uint2 q0 = *(const uint2*)B0;
                const uint2 q1 = *(const uint2*)(B0 + 8);
                bh[nt][0] = __byte_perm(q0.x, q0.y, 0x5410);
                bl[nt][0] = __byte_perm(q0.x, q0.y, 0x7632);
                bh[nt][1] = __byte_perm(q1.x, q1.y, 0x5410);
                bl[nt][1] = __byte_perm(q1.x, q1.y, 0x7632);
            }
            #pragma unroll
            for (int mt = 0; mt < 2; mt++)
                #pragma unroll
                for (int nt = 0; nt < 2; nt++) {
                    mma_bf16(acc[mt][nt], ah[mt], bh[nt][0], bh[nt][1]);
                    mma_bf16(acc[mt][nt], ah[mt], bl[nt][0], bl[nt][1]);
                    mma_bf16(acc[mt][nt], al[mt], bh[nt][0], bh[nt][1]);
                }
        }

        // ---- Epilogue: gelu, dot/ssq partials per colg ----
        #pragma unroll
        for (int mt = 0; mt < 2; mt++) {
            #pragma unroll
            for (int h = 0; h < 2; h++) {
                float dot = 0.f, ssq = 0.f;
                #pragma unroll
                for (int nt = 0; nt < 2; nt++) {
                    #pragma unroll
                    for (int c2 = 0; c2 < 2; c2++) {
                        const int col = colg * 16 + nt * 8 + t4 * 2 + c2;
                        const float z = acc[mt][nt][h * 2 + c2] + mf[MI_SBX + col];
                        const float e = gelu_exact(z);
                        dot += e * mf[MI_STN + col];
                        ssq += e * e;
                    }
                }
                dot += __shfl_xor_sync(FULL, dot, 1);
                dot += __shfl_xor_sync(FULL, dot, 2);
                ssq += __shfl_xor_sync(FULL, ssq, 1);
                ssq += __shfl_xor_sync(FULL, ssq, 2);
                if (t4 == 0) {
                    const int row = rowg * 32 + mt * 16 + h * 8 + g;
                    mf[MI_SDOT + colg * 64 + row] = dot;
                    mf[MI_SSQ  + colg * 64 + row] = ssq;
                }
            }
        }
        __syncthreads();

        if (tid < 64) {
            float dot = 0.f, ssq = 0.f;
            #pragma unroll
            for (int c = 0; c < 8; c++) {
                dot += mf[MI_SDOT + c * 64 + tid];
                ssq += mf[MI_SSQ  + c * 64 + tid];
            }
            const float ps = p[b] * expf(alpha[0]);
            const float a  = ps * dot / fmaxf(sqrtf(ssq), 1e-12f);
            // LN3(a*x) = (x - m) * a * rsqrt(a^2 v + eps) * g3 + b3
            mf[MI_SC + tid] = a * rsqrtf(a * a * mf[MI_SVAR + db + tid] + 1e-6f);
        }
        __syncthreads();

        // ---- Phase 3: residual write (x re-read is L2-hot) ----
        {
            const float4* xb4 = (const float4*)(x + base);
            float4* ob4 = (float4*)(out + base);
            #pragma unroll
            for (int i = tid; i < 64 * 48; i += 512) {
                const int r = i / 48;
                const int c = (i - r * 48) * 4;
                const float4 xv = xb4[i];
                const float m = mf[MI_SMEAN + db + r], scv = mf[MI_SC + r];
                float4 o;
                o.x = 0.5f * xv.x + (xv.x - m) * scv * mf[MI_SG3 + c]     + mf[MI_SB3 + c];
                o.y = 0.5f * xv.y + (xv.y - m) * scv * mf[MI_SG3 + c + 1] + mf[MI_SB3 + c + 1];
                o.z = 0.5f * xv.z + (xv.z - m) * scv * mf[MI_SG3 + c + 2] + mf[MI_SB3 + c + 2];
                o.w = 0.5f * xv.w + (xv.w - m) * scv * mf[MI_SG3 + c + 3] + mf[MI_SB3 + c + 3];
                ob4[i] = o;
            }
        }
        // no barrier: next phase1 writes the other A buffer / other stats half
    }
}

// ---------------------------------------------------------------------------
extern "C" void kernel_launch(void* const* d_in, const int* in_sizes, int n_in,
                              void* d_out, int out_size)
{
    (void)in_sizes; (void)n_in; (void)out_size;
    const float* x     = (const float*)d_in[0];
    const float* token = (const float*)d_in[1];
    const float* p     = (const float*)d_in[2];
    const float* alpha = (const float*)d_in[3];
    const float* ln1_g = (const float*)d_in[4];
    const float* ln1_b = (const float*)d_in[5];
    const float* w_tok = (const float*)d_in[6];
    const float* b_tok = (const float*)d_in[7];
    const float* ln2_g = (const float*)d_in[8];
    const float* ln2_b = (const float*)d_in[9];
    const float* w_x   = (const float*)d_in[10];
    const float* b_x   = (const float*)d_in[11];
    const float* ln3_g = (const float*)d_in[12];
    const float* ln3_b = (const float*)d_in[13];
    float* out = (float*)d_out;

    token_proj<<<dim3(4, 32), 256>>>(token, ln1_g, ln1_b, w_tok, b_tok);
    token_norm<<<32, 128>>>();

    static int nsm = 0;
    if (nsm == 0) {
        cudaDeviceGetAttribute(&nsm, cudaDevAttrMultiProcessorCount, 0);
        if (nsm <= 0) nsm = 148;
    }
    const size_t smem = SMEM_WORDS * sizeof(float);
    cudaFuncSetAttribute(main_kernel, cudaFuncAttributeMaxDynamicSharedMemorySize,
                         (int)smem);
    main_kernel<<<nsm, 512, smem>>>(x, p, alpha, ln2_g, ln2_b, w_x, b_x,
                                    ln3_g, ln3_b, out);
}

// round 6
// speedup vs baseline: 1.6814x; 1.0957x over previous
#include <cuda_runtime.h>
#include <cuda_bf16.h>
#include <math.h>
#include <stdint.h>

#define FULL 0xffffffffu

__device__ float g_y[32 * 128];   // gelu(LN1(token) @ w_tok + b_tok), unnormalized

__device__ __forceinline__ float gelu_exact(float z) {
    return 0.5f * z * (1.0f + erff(z * 0.70710678118654752f));
}

// pack value as (bf16_hi | bf16_lo<<16); hi+lo == v to ~2^-16 rel
__device__ __forceinline__ uint32_t pack_hl(float v) {
    __nv_bfloat16 h = __float2bfloat16(v);
    float hf = __bfloat162float(h);
    __nv_bfloat16 l = __float2bfloat16(v - hf);
    return (uint32_t)__bfloat16_as_ushort(h)
         | ((uint32_t)__bfloat16_as_ushort(l) << 16);
}

__device__ __forceinline__ void mma_bf16(float* c, const uint32_t* a,
                                         uint32_t b0, uint32_t b1) {
    asm volatile(
        "mma.sync.aligned.m16n8k16.row.col.f32.bf16.bf16.f32 "
        "{%0,%1,%2,%3}, {%4,%5,%6,%7}, {%8,%9}, {%0,%1,%2,%3};\n"
        : "+f"(c[0]), "+f"(c[1]), "+f"(c[2]), "+f"(c[3])
        : "r"(a[0]), "r"(a[1]), "r"(a[2]), "r"(a[3]), "r"(b0), "r"(b1));
}

// ---------------------------------------------------------------------------
// Kernel 1: token projection. Grid (4, 32), 512 threads.
// g_y[b][n] = gelu(LN1(token[b]) @ w_tok[:,n] + b_tok[n])
// ---------------------------------------------------------------------------
__global__ void __launch_bounds__(512) token_proj(
    const float* __restrict__ token,
    const float* __restrict__ ln1_g,
    const float* __restrict__ ln1_b,
    const float* __restrict__ w_tok,
    const float* __restrict__ b_tok)
{
    __shared__ float st[768];
    __shared__ float sred[16];
    __shared__ float sredq[16];
    __shared__ float spart[16][33];

    const int b = blockIdx.y, nq = blockIdx.x;
    const int tid = threadIdx.x;
    const int wid = tid >> 5, lane = tid & 31;
    const float* trow = token + b * 768;

    float s = 0.f, sq = 0.f;
    for (int i = tid; i < 768; i += 512) {
        float v = trow[i];
        st[i] = v;
        s += v; sq += v * v;
    }
    #pragma unroll
    for (int o = 16; o; o >>= 1) {
        s  += __shfl_down_sync(FULL, s,  o);
        sq += __shfl_down_sync(FULL, sq, o);
    }
    if (lane == 0) { sred[wid] = s; sredq[wid] = sq; }
    __syncthreads();
    if (tid == 0) {
        float ts = 0.f, tq = 0.f;
        #pragma unroll
        for (int i = 0; i < 16; i++) { ts += sred[i]; tq += sredq[i]; }
        sred[0] = ts; sredq[0] = tq;
    }
    __syncthreads();
    const float mean = sred[0] * (1.0f / 768.0f);
    const float var  = sredq[0] * (1.0f / 768.0f) - mean * mean;
    const float rstd = rsqrtf(var + 1e-6f);
    for (int i = tid; i < 768; i += 512)
        st[i] = (st[i] - mean) * rstd * ln1_g[i] + ln1_b[i];
    __syncthreads();

    // GEMV: 512 threads = 32 cols x 16 k-slices of 48
    const int col = nq * 32 + lane;
    const int ks = wid;
    float acc = 0.f;
    const float* sp = st + ks * 48;
    const float* wp = w_tok + (size_t)(ks * 48) * 128 + col;
    #pragma unroll 8
    for (int kk = 0; kk < 48; kk++)
        acc += sp[kk] * wp[(size_t)kk * 128];
    spart[ks][lane] = acc;
    __syncthreads();

    if (tid < 32) {
        float z = b_tok[nq * 32 + tid];
        #pragma unroll
        for (int i = 0; i < 16; i++) z += spart[i][tid];
        g_y[b * 128 + nq * 32 + tid] = gelu_exact(z);
    }
}

// ---------------------------------------------------------------------------
// Kernel 2: persistent fused main path. 512 thr (16 warps), 1 CTA/SM.
// 64-row tiles, double-buffered As, reg prefetch, reg-resident x for phase 3.
// GEMM 64x128x192 bf16 hi/lo 3-term; warp tile 32x16 (rowg=wid&1, colg=wid>>1).
// ---------------------------------------------------------------------------
#define APAD 200
#define NTILES 2048
#define MI_SMEAN 0
#define MI_SVAR  128
#define MI_SC    256
#define MI_SDOT  320
#define MI_SSQ   832
#define MI_STN   1344
#define MI_SBX   1472
#define MI_SG2   1600
#define MI_SB2   1792
#define MI_SG3   1984
#define MI_SB3   2176
#define MI_INVNY 2368
#define MF_WORDS 2400
#define SMEM_WORDS (2 * 64 * APAD + 128 * APAD + MF_WORDS)

__global__ void __launch_bounds__(512, 1) main_kernel(
    const float* __restrict__ x,
    const float* __restrict__ p,
    const float* __restrict__ alpha,
    const float* __restrict__ ln2_g, const float* __restrict__ ln2_b,
    const float* __restrict__ w_x,  const float* __restrict__ b_x,
    const float* __restrict__ ln3_g, const float* __restrict__ ln3_b,
    float* __restrict__ out)
{
    extern __shared__ float sm[];
    uint32_t* Asu = (uint32_t*)sm;            // [2][64][APAD] packed hi/lo
    uint32_t* Bsu = Asu + 2 * 64 * APAD;      // [128 n][APAD k] packed hi/lo
    float* mf = (float*)(Bsu + 128 * APAD);

    const int tid = threadIdx.x;
    const int wid = tid >> 5, lane = tid & 31;
    const int g = lane >> 2, t4 = lane & 3;
    const int rowg = wid & 1, colg = wid >> 1;

    // ---- persistent setup ----
    if (tid < 128) mf[MI_SBX + tid] = b_x[tid];
    if (tid < 192) {
        mf[MI_SG2 + tid] = ln2_g[tid]; mf[MI_SB2 + tid] = ln2_b[tid];
        mf[MI_SG3 + tid] = ln3_g[tid]; mf[MI_SB3 + tid] = ln3_b[tid];
    }
    {   // B[n][k] = w_x[k][n]; lanes iterate k -> conflict-free STS
        const float4* w4 = (const float4*)w_x;
        #pragma unroll
        for (int nn = wid; nn < 32; nn += 16) {
            for (int k = lane; k < 192; k += 32) {
                float4 v = w4[(size_t)k * 32 + nn];
                Bsu[(nn * 4 + 0) * APAD + k] = pack_hl(v.x);
                Bsu[(nn * 4 + 1) * APAD + k] = pack_hl(v.y);
                Bsu[(nn * 4 + 2) * APAD + k] = pack_hl(v.z);
                Bsu[(nn * 4 + 3) * APAD + k] = pack_hl(v.w);
            }
        }
    }
    {   // 1/max(|y|,eps) per batch; warp handles 2 batches (16 lanes each)
        const int bb = wid * 2 + (lane >> 4);
        const int l16 = lane & 15;
        float q = 0.f;
        #pragma unroll
        for (int jj = 0; jj < 8; jj++) {
            const float v = g_y[bb * 128 + l16 + jj * 16];
            q += v * v;
        }
        #pragma unroll
        for (int o = 8; o; o >>= 1) q += __shfl_down_sync(FULL, q, o, 16);
        if (l16 == 0) mf[MI_INVNY + bb] = 1.0f / fmaxf(sqrtf(q), 1e-12f);
    }

    // ---- prologue prefetch of first tile ----
    float2 v[4][3], vn[4][3];
    {
        const float2* xr = (const float2*)(x + ((size_t)blockIdx.x * 64 + wid * 4) * 192);
        #pragma unroll
        for (int rr = 0; rr < 4; rr++)
            #pragma unroll
            for (int j = 0; j < 3; j++)
                v[rr][j] = xr[rr * 96 + lane + 32 * j];
    }

    int it = 0;
    for (int tile = blockIdx.x; tile < NTILES; tile += gridDim.x, it++) {
        const int db = (it & 1) * 64;
        const int Abase = (it & 1) * 64 * APAD;
        const int b = tile >> 6;
        const size_t base = (size_t)tile * 64 * 192;

        if (tid < 128) mf[MI_STN + tid] = g_y[b * 128 + tid];

        // ---- Phase 1: LN2 + hi/lo pack from registers into As ----
        #pragma unroll
        for (int rr = 0; rr < 4; rr++) {
            const int r = wid * 4 + rr;
            float s = 0.f, sq = 0.f;
            #pragma unroll
            for (int j = 0; j < 3; j++) {
                s += v[rr][j].x + v[rr][j].y;
                sq += v[rr][j].x * v[rr][j].x + v[rr][j].y * v[rr][j].y;
            }
            #pragma unroll
            for (int o = 16; o; o >>= 1) {
                s  += __shfl_down_sync(FULL, s,  o);
                sq += __shfl_down_sync(FULL, sq, o);
            }
            s  = __shfl_sync(FULL, s, 0);
            sq = __shfl_sync(FULL, sq, 0);
            const float mean = s * (1.0f / 192.0f);
            const float var  = sq * (1.0f / 192.0f) - mean * mean;
            const float rstd = rsqrtf(var + 1e-6f);
            if (lane == 0) { mf[MI_SMEAN + db + r] = mean; mf[MI_SVAR + db + r] = var; }
            #pragma unroll
            for (int j = 0; j < 3; j++) {
                const int c = 2 * lane + 64 * j;
                uint2 w;
                w.x = pack_hl((v[rr][j].x - mean) * rstd * mf[MI_SG2 + c]     + mf[MI_SB2 + c]);
                w.y = pack_hl((v[rr][j].y - mean) * rstd * mf[MI_SG2 + c + 1] + mf[MI_SB2 + c + 1]);
                *(uint2*)&Asu[Abase + r * APAD + c] = w;
            }
        }
        __syncthreads();

        // ---- prefetch next tile's x into registers (covered by GEMM) ----
        {
            int nxt = tile + gridDim.x;
            if (nxt >= NTILES) nxt = tile;
            const float2* xr = (const float2*)(x + ((size_t)nxt * 64 + wid * 4) * 192);
            #pragma unroll
            for (int rr = 0; rr < 4; rr++)
                #pragma unroll
                for (int j = 0; j < 3; j++)
                    vn[rr][j] = xr[rr * 96 + lane + 32 * j];
        }

        // ---- Phase 2: GEMM warp tile 32x16, 12 k16-steps, 3 terms ----
        float acc[2][2][4];
        #pragma unroll
        for (int mt = 0; mt < 2; mt++)
            #pragma unroll
            for (int nt = 0; nt < 2; nt++)
                #pragma unroll
                for (int i = 0; i < 4; i++) acc[mt][nt][i] = 0.f;

        #pragma unroll
        for (int ks = 0; ks < 12; ks++) {
            const int k0 = ks * 16 + 2 * t4;
            uint32_t ah[2][4], al[2][4];
            #pragma unroll
            for (int mt = 0; mt < 2; mt++) {
                const uint32_t* A0 = &Asu[Abase + (rowg * 32 + mt * 16 + g) * APAD + k0];
                const uint2 p0 = *(const uint2*)A0;
                const uint2 p1 = *(const uint2*)(A0 + 8 * APAD);
                const uint2 p2 = *(const uint2*)(A0 + 8);
                const uint2 p3 = *(const uint2*)(A0 + 8 * APAD + 8);
                ah[mt][0] = __byte_perm(p0.x, p0.y, 0x5410);
                al[mt][0] = __byte_perm(p0.x, p0.y, 0x7632);
                ah[mt][1] = __byte_perm(p1.x, p1.y, 0x5410);
                al[mt][1] = __byte_perm(p1.x, p1.y, 0x7632);
                ah[mt][2] = __byte_perm(p2.x, p2.y, 0x5410);
                al[mt][2] = __byte_perm(p2.x, p2.y, 0x7632);
                ah[mt][3] = __byte_perm(p3.x, p3.y, 0x5410);
                al[mt][3] = __byte_perm(p3.x, p3.y, 0x7632);
            }
            uint32_t bh[2][2], bl[2][2];
            #pragma unroll
            for (int nt = 0; nt < 2; nt++) {
                const uint32_t* B0 = &Bsu[(colg * 16 + nt * 8 + g) * APAD + k0];
                const uint2 q0 = *(const uint2*)B0;
                const uint2 q1 = *(const uint2*)(B0 + 8);
                bh[nt][0] = __byte_perm(q0.x, q0.y, 0x5410);
                bl[nt][0] = __byte_perm(q0.x, q0.y, 0x7632);
                bh[nt][1] = __byte_perm(q1.x, q1.y, 0x5410);
                bl[nt][1] = __byte_perm(q1.x, q1.y, 0x7632);
            }
            #pragma unroll
            for (int mt = 0; mt < 2; mt++)
                #pragma unroll
                for (int nt = 0; nt < 2; nt++) {
                    mma_bf16(acc[mt][nt], ah[mt], bh[nt][0], bh[nt][1]);
                    mma_bf16(acc[mt][nt], ah[mt], bl[nt][0], bl[nt][1]);
                    mma_bf16(acc[mt][nt], al[mt], bh[nt][0], bh[nt][1]);
                }
        }

        // ---- Epilogue: gelu, dot(.,y)/ssq partials per colg ----
        #pragma unroll
        for (int mt = 0; mt < 2; mt++) {
            #pragma unroll
            for (int h = 0; h < 2; h++) {
                float dot = 0.f, ssq = 0.f;
                #pragma unroll
                for (int nt = 0; nt < 2; nt++) {
                    #pragma unroll
                    for (int c2 = 0; c2 < 2; c2++) {
                        const int col = colg * 16 + nt * 8 + t4 * 2 + c2;
                        const float z = acc[mt][nt][h * 2 + c2] + mf[MI_SBX + col];
                        const float e = gelu_exact(z);
                        dot += e * mf[MI_STN + col];
                        ssq += e * e;
                    }
                }
                dot += __shfl_xor_sync(FULL, dot, 1);
                dot += __shfl_xor_sync(FULL, dot, 2);
                ssq += __shfl_xor_sync(FULL, ssq, 1);
                ssq += __shfl_xor_sync(FULL, ssq, 2);
                if (t4 == 0) {
                    const int row = rowg * 32 + mt * 16 + h * 8 + g;
                    mf[MI_SDOT + colg * 64 + row] = dot;
                    mf[MI_SSQ  + colg * 64 + row] = ssq;
                }
            }
        }
        __syncthreads();

        if (tid < 64) {
            float dot = 0.f, ssq = 0.f;
            #pragma unroll
            for (int c = 0; c < 8; c++) {
                dot += mf[MI_SDOT + c * 64 + tid];
                ssq += mf[MI_SSQ  + c * 64 + tid];
            }
            const float ps = p[b] * expf(alpha[0]) * mf[MI_INVNY + b];
            const float a  = ps * dot / fmaxf(sqrtf(ssq), 1e-12f);
            // LN3(a*x) = (x - m) * a * rsqrt(a^2 v + eps) * g3 + b3
            mf[MI_SC + tid] = a * rsqrtf(a * a * mf[MI_SVAR + db + tid] + 1e-6f);
        }
        __syncthreads();

        // ---- Phase 3: residual write from registers (no x re-read) ----
        {
            float* ob = out + base;
            #pragma unroll
            for (int rr = 0; rr < 4; rr++) {
                const int r = wid * 4 + rr;
                const float m = mf[MI_SMEAN + db + r], scv = mf[MI_SC + r];
                #pragma unroll
                for (int j = 0; j < 3; j++) {
                    const int c = 2 * lane + 64 * j;
                    const float2 xv = v[rr][j];
                    float2 o;
                    o.x = 0.5f * xv.x + (xv.x - m) * scv * mf[MI_SG3 + c]     + mf[MI_SB3 + c];
                    o.y = 0.5f * xv.y + (xv.y - m) * scv * mf[MI_SG3 + c + 1] + mf[MI_SB3 + c + 1];
                    *(float2*)&ob[r * 192 + c] = o;
                }
            }
        }
        // rotate prefetched tile into current
        #pragma unroll
        for (int rr = 0; rr < 4; rr++)
            #pragma unroll
            for (int j = 0; j < 3; j++)
                v[rr][j] = vn[rr][j];
        // no barrier: next phase1 writes the other A buffer / other stats half
    }
}

// ---------------------------------------------------------------------------
extern "C" void kernel_launch(void* const* d_in, const int* in_sizes, int n_in,
                              void* d_out, int out_size)
{
    (void)in_sizes; (void)n_in; (void)out_size;
    const float* x     = (const float*)d_in[0];
    const float* token = (const float*)d_in[1];
    const float* p     = (const float*)d_in[2];
    const float* alpha = (const float*)d_in[3];
    const float* ln1_g = (const float*)d_in[4];
    const float* ln1_b = (const float*)d_in[5];
    const float* w_tok = (const float*)d_in[6];
    const float* b_tok = (const float*)d_in[7];
    const float* ln2_g = (const float*)d_in[8];
    const float* ln2_b = (const float*)d_in[9];
    const float* w_x   = (const float*)d_in[10];
    const float* b_x   = (const float*)d_in[11];
    const float* ln3_g = (const float*)d_in[12];
    const float* ln3_b = (const float*)d_in[13];
    float* out = (float*)d_out;

    token_proj<<<dim3(4, 32), 512>>>(token, ln1_g, ln1_b, w_tok, b_tok);

    static int nsm = 0;
    if (nsm == 0) {
        cudaDeviceGetAttribute(&nsm, cudaDevAttrMultiProcessorCount, 0);
        if (nsm <= 0) nsm = 148;
    }
    const size_t smem = SMEM_WORDS * sizeof(float);
    cudaFuncSetAttribute(main_kernel, cudaFuncAttributeMaxDynamicSharedMemorySize,
                         (int)smem);
    main_kernel<<<nsm, 512, smem>>>(x, p, alpha, ln2_g, ln2_b, w_x, b_x,
                                    ln3_g, ln3_b, out);
}

// round 8
// speedup vs baseline: 1.8722x; 1.1135x over previous
#include <cuda_runtime.h>
#include <cuda_bf16.h>
#include <math.h>
#include <stdint.h>

#define FULL 0xffffffffu

__device__ float g_y[32 * 128];   // gelu(LN1(token) @ w_tok + b_tok), unnormalized

__device__ __forceinline__ float gelu_exact(float z) {
    return 0.5f * z * (1.0f + erff(z * 0.70710678118654752f));
}

__device__ __forceinline__ uint32_t smem_u32(const void* p) {
    uint32_t a;
    asm("{ .reg .u64 t; cvta.to.shared.u64 t, %1; cvt.u32.u64 %0, t; }"
        : "=r"(a) : "l"(p));
    return a;
}

__device__ __forceinline__ void ldsm4(uint32_t* r, uint32_t addr) {
    asm volatile("ldmatrix.sync.aligned.m8n8.x4.shared.b16 {%0,%1,%2,%3}, [%4];"
        : "=r"(r[0]), "=r"(r[1]), "=r"(r[2]), "=r"(r[3]) : "r"(addr));
}

__device__ __forceinline__ void mma_bf16(float* c, const uint32_t* a,
                                         uint32_t b0, uint32_t b1) {
    asm volatile(
        "mma.sync.aligned.m16n8k16.row.col.f32.bf16.bf16.f32 "
        "{%0,%1,%2,%3}, {%4,%5,%6,%7}, {%8,%9}, {%0,%1,%2,%3};\n"
        : "+f"(c[0]), "+f"(c[1]), "+f"(c[2]), "+f"(c[3])
        : "r"(a[0]), "r"(a[1]), "r"(a[2]), "r"(a[3]), "r"(b0), "r"(b1));
}

// ---------------------------------------------------------------------------
// Kernel 1: token projection. Grid (4, 32), 512 threads.
// g_y[b][n] = gelu(LN1(token[b]) @ w_tok[:,n] + b_tok[n])
// ---------------------------------------------------------------------------
__global__ void __launch_bounds__(512) token_proj(
    const float* __restrict__ token,
    const float* __restrict__ ln1_g,
    const float* __restrict__ ln1_b,
    const float* __restrict__ w_tok,
    const float* __restrict__ b_tok)
{
    __shared__ float st[768];
    __shared__ float sred[16];
    __shared__ float sredq[16];
    __shared__ float spart[16][33];

    const int b = blockIdx.y, nq = blockIdx.x;
    const int tid = threadIdx.x;
    const int wid = tid >> 5, lane = tid & 31;
    const float* trow = token + b * 768;

    float s = 0.f, sq = 0.f;
    for (int i = tid; i < 768; i += 512) {
        float v = trow[i];
        st[i] = v;
        s += v; sq += v * v;
    }
    #pragma unroll
    for (int o = 16; o; o >>= 1) {
        s  += __shfl_down_sync(FULL, s,  o);
        sq += __shfl_down_sync(FULL, sq, o);
    }
    if (lane == 0) { sred[wid] = s; sredq[wid] = sq; }
    __syncthreads();
    if (tid == 0) {
        float ts = 0.f, tq = 0.f;
        #pragma unroll
        for (int i = 0; i < 16; i++) { ts += sred[i]; tq += sredq[i]; }
        sred[0] = ts; sredq[0] = tq;
    }
    __syncthreads();
    const float mean = sred[0] * (1.0f / 768.0f);
    const float var  = sredq[0] * (1.0f / 768.0f) - mean * mean;
    const float rstd = rsqrtf(var + 1e-6f);
    for (int i = tid; i < 768; i += 512)
        st[i] = (st[i] - mean) * rstd * ln1_g[i] + ln1_b[i];
    __syncthreads();

    // GEMV: 512 threads = 32 cols x 16 k-slices of 48; full unroll -> 48 LDG in flight
    const int col = nq * 32 + lane;
    const int ks = wid;
    float acc = 0.f;
    const float* sp = st + ks * 48;
    const float* wp = w_tok + (size_t)(ks * 48) * 128 + col;
    #pragma unroll
    for (int kk = 0; kk < 48; kk++)
        acc += sp[kk] * wp[(size_t)kk * 128];
    spart[ks][lane] = acc;
    __syncthreads();

    if (tid < 32) {
        float z = b_tok[nq * 32 + tid];
        #pragma unroll
        for (int i = 0; i < 16; i++) z += spart[i][tid];
        g_y[b * 128 + nq * 32 + tid] = gelu_exact(z);
    }
}

// ---------------------------------------------------------------------------
// Kernel 2: persistent fused main path. 512 thr (16 warps), 1 CTA/SM.
// 64-row tiles, double-buffered A (separate bf16 hi/lo planes), ldmatrix
// fragment loads, reg prefetch, reg-resident x for phase 3.
// GEMM 64x128x192 bf16 hi/lo 3-term; warp tile 32x16 (rowg=wid&1, colg=wid>>1).
//
// SMEM byte layout:
//   [0, 102400):   A: 2 bufs x (hi 64x400 | lo 64x400)
//   [102400, 204800): B: hi 128x400 | lo 128x400
//   [204800, ...): mf float region
// Row stride 400 B: 192 bf16 (384 B) + 16 pad -> LDSM rows conflict-free.
// ---------------------------------------------------------------------------
#define A_STRIDE 400
#define A_PLANE  25600
#define A_BUF    51200
#define OFF_B    102400
#define B_PLANE  51200
#define OFF_MF   204800
#define NTILES 2048
#define MI_SMEAN 0
#define MI_SVAR  128
#define MI_SC    256
#define MI_SDOT  320
#define MI_SSQ   832
#define MI_STN   1344
#define MI_SBX   1472
#define MI_SG2   1600
#define MI_SB2   1792
#define MI_SG3   1984
#define MI_SB3   2176
#define MI_INVNY 2368
#define MF_WORDS 2400
#define SMEM_BYTES (OFF_MF + MF_WORDS * 4)

__global__ void __launch_bounds__(512, 1) main_kernel(
    const float* __restrict__ x,
    const float* __restrict__ p,
    const float* __restrict__ alpha,
    const float* __restrict__ ln2_g, const float* __restrict__ ln2_b,
    const float* __restrict__ w_x,  const float* __restrict__ b_x,
    const float* __restrict__ ln3_g, const float* __restrict__ ln3_b,
    float* __restrict__ out)
{
    extern __shared__ char smc[];
    const uint32_t sbase = smem_u32(smc);
    float* mf = (float*)(smc + OFF_MF);

    const int tid = threadIdx.x;
    const int wid = tid >> 5, lane = tid & 31;
    const int g = lane >> 2, t4 = lane & 3;
    const int rowg = wid & 1, colg = wid >> 1;

    // ---- persistent setup ----
    if (tid < 128) mf[MI_SBX + tid] = b_x[tid];
    if (tid < 192) {
        mf[MI_SG2 + tid] = ln2_g[tid]; mf[MI_SB2 + tid] = ln2_b[tid];
        mf[MI_SG3 + tid] = ln3_g[tid]; mf[MI_SB3 + tid] = ln3_b[tid];
    }
    {   // B[n][k] = w_x[k][n] split into hi/lo bf16 planes (coalesced LDG)
        for (int i = tid; i < 192 * 128; i += 512) {
            const int k = i >> 7, n = i & 127;
            const float vv = w_x[i];
            __nv_bfloat16 h = __float2bfloat16(vv);
            __nv_bfloat16 l = __float2bfloat16(vv - __bfloat162float(h));
            *(__nv_bfloat16*)(smc + OFF_B + n * A_STRIDE + k * 2) = h;
            *(__nv_bfloat16*)(smc + OFF_B + B_PLANE + n * A_STRIDE + k * 2) = l;
        }
    }
    {   // 1/max(|y|,eps) per batch; warp handles 2 batches (16 lanes each)
        const int bb = wid * 2 + (lane >> 4);
        const int l16 = lane & 15;
        float q = 0.f;
        #pragma unroll
        for (int jj = 0; jj < 8; jj++) {
            const float v = g_y[bb * 128 + l16 + jj * 16];
            q += v * v;
        }
        #pragma unroll
        for (int o = 8; o; o >>= 1) q += __shfl_down_sync(FULL, q, o, 16);
        if (l16 == 0) mf[MI_INVNY + bb] = 1.0f / fmaxf(sqrtf(q), 1e-12f);
    }

    // per-thread ldmatrix address components (tile-invariant parts)
    // A: r0 rows0-7 k0 | r1 rows8-15 k0 | r2 rows0-7 k+16B | r3 rows8-15 k+16B
    const uint32_t aRowOff = (uint32_t)((rowg * 32 + (lane & 15)) * A_STRIDE
                                        + ((lane >> 4) ? 16 : 0));
    // B: r0 n0-7 k0 | r1 n0-7 k+16B | r2 n8-15 k0 | r3 n8-15 k+16B
    const uint32_t bHi = sbase + OFF_B
        + (uint32_t)((colg * 16 + (lane & 7) + ((lane >> 4) & 1) * 8) * A_STRIDE
                     + ((lane >> 3) & 1) * 16);
    const uint32_t bLo = bHi + B_PLANE;

    // ---- prologue prefetch of first tile ----
    float2 v[4][3], vn[4][3];
    {
        const float2* xr = (const float2*)(x + ((size_t)blockIdx.x * 64 + wid * 4) * 192);
        #pragma unroll
        for (int rr = 0; rr < 4; rr++)
            #pragma unroll
            for (int j = 0; j < 3; j++)
                v[rr][j] = xr[rr * 96 + lane + 32 * j];
    }

    int it = 0;
    for (int tile = blockIdx.x; tile < NTILES; tile += gridDim.x, it++) {
        const int db = (it & 1) * 64;
        const uint32_t Abase = (uint32_t)((it & 1) * A_BUF);
        const int b = tile >> 6;
        const size_t base = (size_t)tile * 64 * 192;

        if (tid < 128) mf[MI_STN + tid] = g_y[b * 128 + tid];

        // ---- Phase 1: LN2 + bf16 hi/lo planes from registers ----
        char* AhiP = smc + Abase;
        char* AloP = AhiP + A_PLANE;
        #pragma unroll
        for (int rr = 0; rr < 4; rr++) {
            const int r = wid * 4 + rr;
            float s = 0.f, sq = 0.f;
            #pragma unroll
            for (int j = 0; j < 3; j++) {
                s += v[rr][j].x + v[rr][j].y;
                sq += v[rr][j].x * v[rr][j].x + v[rr][j].y * v[rr][j].y;
            }
            #pragma unroll
            for (int o = 16; o; o >>= 1) {
                s  += __shfl_down_sync(FULL, s,  o);
                sq += __shfl_down_sync(FULL, sq, o);
            }
            s  = __shfl_sync(FULL, s, 0);
            sq = __shfl_sync(FULL, sq, 0);
            const float mean = s * (1.0f / 192.0f);
            const float var  = sq * (1.0f / 192.0f) - mean * mean;
            const float rstd = rsqrtf(var + 1e-6f);
            if (lane == 0) { mf[MI_SMEAN + db + r] = mean; mf[MI_SVAR + db + r] = var; }
            #pragma unroll
            for (int j = 0; j < 3; j++) {
                const int c = 2 * lane + 64 * j;
                const float a0 = (v[rr][j].x - mean) * rstd * mf[MI_SG2 + c]     + mf[MI_SB2 + c];
                const float a1 = (v[rr][j].y - mean) * rstd * mf[MI_SG2 + c + 1] + mf[MI_SB2 + c + 1];
                __nv_bfloat162 h2 = __floats2bfloat162_rn(a0, a1);
                __nv_bfloat162 l2 = __floats2bfloat162_rn(a0 - __low2float(h2),
                                                          a1 - __high2float(h2));
                const int off = r * A_STRIDE + 4 * lane + 128 * j;
                *(uint32_t*)(AhiP + off) = *(uint32_t*)&h2;
                *(uint32_t*)(AloP + off) = *(uint32_t*)&l2;
            }
        }
        __syncthreads();

        // ---- prefetch next tile's x (covered by GEMM) ----
        {
            int nxt = tile + gridDim.x;
            if (nxt >= NTILES) nxt = tile;
            const float2* xr = (const float2*)(x + ((size_t)nxt * 64 + wid * 4) * 192);
            #pragma unroll
            for (int rr = 0; rr < 4; rr++)
                #pragma unroll
                for (int j = 0; j < 3; j++)
                    vn[rr][j] = xr[rr * 96 + lane + 32 * j];
        }

        // ---- Phase 2: GEMM warp tile 32x16, 12 k16-steps, 3 terms ----
        const uint32_t aHi0 = sbase + Abase + aRowOff;
        const uint32_t aHi1 = aHi0 + 16 * A_STRIDE;

        float acc[2][2][4];
        #pragma unroll
        for (int mt = 0; mt < 2; mt++)
            #pragma unroll
            for (int nt = 0; nt < 2; nt++)
                #pragma unroll
                for (int i = 0; i < 4; i++) acc[mt][nt][i] = 0.f;

        #pragma unroll
        for (int ks = 0; ks < 12; ks++) {
            const uint32_t kb = ks * 32;
            uint32_t aH0[4], aH1[4], aL0[4], aL1[4], bH[4], bL[4];
            ldsm4(aH0, aHi0 + kb);
            ldsm4(aH1, aHi1 + kb);
            ldsm4(bH,  bHi  + kb);
            ldsm4(aL0, aHi0 + A_PLANE + kb);
            ldsm4(aL1, aHi1 + A_PLANE + kb);
            ldsm4(bL,  bLo  + kb);
            mma_bf16(acc[0][0], aH0, bH[0], bH[1]);
            mma_bf16(acc[0][1], aH0, bH[2], bH[3]);
            mma_bf16(acc[1][0], aH1, bH[0], bH[1]);
            mma_bf16(acc[1][1], aH1, bH[2], bH[3]);
            mma_bf16(acc[0][0], aH0, bL[0], bL[1]);
            mma_bf16(acc[0][1], aH0, bL[2], bL[3]);
            mma_bf16(acc[1][0], aH1, bL[0], bL[1]);
            mma_bf16(acc[1][1], aH1, bL[2], bL[3]);
            mma_bf16(acc[0][0], aL0, bH[0], bH[1]);
            mma_bf16(acc[0][1], aL0, bH[2], bH[3]);
            mma_bf16(acc[1][0], aL1, bH[0], bH[1]);
            mma_bf16(acc[1][1], aL1, bH[2], bH[3]);
        }

        // ---- Epilogue: gelu, dot(.,y)/ssq partials per colg ----
        #pragma unroll
        for (int mt = 0; mt < 2; mt++) {
            #pragma unroll
            for (int h = 0; h < 2; h++) {
                float dot = 0.f, ssq = 0.f;
                #pragma unroll
                for (int nt = 0; nt < 2; nt++) {
                    #pragma unroll
                    for (int c2 = 0; c2 < 2; c2++) {
                        const int col = colg * 16 + nt * 8 + t4 * 2 + c2;
                        const float z = acc[mt][nt][h * 2 + c2] + mf[MI_SBX + col];
                        const float e = gelu_exact(z);
                        dot += e * mf[MI_STN + col];
                        ssq += e * e;
                    }
                }
                dot += __shfl_xor_sync(FULL, dot, 1);
                dot += __shfl_xor_sync(FULL, dot, 2);
                ssq += __shfl_xor_sync(FULL, ssq, 1);
                ssq += __shfl_xor_sync(FULL, ssq, 2);
                if (t4 == 0) {
                    const int row = rowg * 32 + mt * 16 + h * 8 + g;
                    mf[MI_SDOT + colg * 64 + row] = dot;
                    mf[MI_SSQ  + colg * 64 + row] = ssq;
                }
            }
        }
        __syncthreads();

        if (tid < 64) {
            float dot = 0.f, ssq = 0.f;
            #pragma unroll
            for (int c = 0; c < 8; c++) {
                dot += mf[MI_SDOT + c * 64 + tid];
                ssq += mf[MI_SSQ  + c * 64 + tid];
            }
            const float ps = p[b] * expf(alpha[0]) * mf[MI_INVNY + b];
            const float a  = ps * dot / fmaxf(sqrtf(ssq), 1e-12f);
            // LN3(a*x) = (x - m) * a * rsqrt(a^2 v + eps) * g3 + b3
            mf[MI_SC + tid] = a * rsqrtf(a * a * mf[MI_SVAR + db + tid] + 1e-6f);
        }
        __syncthreads();

        // ---- Phase 3: residual write from registers (no x re-read) ----
        {
            float* ob = out + base;
            #pragma unroll
            for (int rr = 0; rr < 4; rr++) {
                const int r = wid * 4 + rr;
                const float m = mf[MI_SMEAN + db + r], scv = mf[MI_SC + r];
                #pragma unroll
                for (int j = 0; j < 3; j++) {
                    const int c = 2 * lane + 64 * j;
                    const float2 xv = v[rr][j];
                    float2 o;
                    o.x = 0.5f * xv.x + (xv.x - m) * scv * mf[MI_SG3 + c]     + mf[MI_SB3 + c];
                    o.y = 0.5f * xv.y + (xv.y - m) * scv * mf[MI_SG3 + c + 1] + mf[MI_SB3 + c + 1];
                    *(float2*)&ob[r * 192 + c] = o;
                }
            }
        }
        // rotate prefetched tile into current
        #pragma unroll
        for (int rr = 0; rr < 4; rr++)
            #pragma unroll
            for (int j = 0; j < 3; j++)
                v[rr][j] = vn[rr][j];
        // no barrier: next phase1 writes the other A buffer / other stats half
    }
}

// ---------------------------------------------------------------------------
extern "C" void kernel_launch(void* const* d_in, const int* in_sizes, int n_in,
                              void* d_out, int out_size)
{
    (void)in_sizes; (void)n_in; (void)out_size;
    const float* x     = (const float*)d_in[0];
    const float* token = (const float*)d_in[1];
    const float* p     = (const float*)d_in[2];
    const float* alpha = (const float*)d_in[3];
    const float* ln1_g = (const float*)d_in[4];
    const float* ln1_b = (const float*)d_in[5];
    const float* w_tok = (const float*)d_in[6];
    const float* b_tok = (const float*)d_in[7];
    const float* ln2_g = (const float*)d_in[8];
    const float* ln2_b = (const float*)d_in[9];
    const float* w_x   = (const float*)d_in[10];
    const float* b_x   = (const float*)d_in[11];
    const float* ln3_g = (const float*)d_in[12];
    const float* ln3_b = (const float*)d_in[13];
    float* out = (float*)d_out;

    token_proj<<<dim3(4, 32), 512>>>(token, ln1_g, ln1_b, w_tok, b_tok);

    static int nsm = 0;
    if (nsm == 0) {
        cudaDeviceGetAttribute(&nsm, cudaDevAttrMultiProcessorCount, 0);
        if (nsm <= 0) nsm = 148;
    }
    cudaFuncSetAttribute(main_kernel, cudaFuncAttributeMaxDynamicSharedMemorySize,
                         SMEM_BYTES);
    main_kernel<<<nsm, 512, SMEM_BYTES>>>(x, p, alpha, ln2_g, ln2_b, w_x, b_x,
                                          ln3_g, ln3_b, out);
}

// round 10
// speedup vs baseline: 2.0482x; 1.0940x over previous
#include <cuda_runtime.h>
#include <cuda_bf16.h>
#include <math.h>
#include <stdint.h>

#define FULL 0xffffffffu

__device__ float g_y[32 * 128];   // gelu(LN1(token) @ w_tok + b_tok), unnormalized

__device__ __forceinline__ float gelu_exact(float z) {
    return 0.5f * z * (1.0f + erff(z * 0.70710678118654752f));
}

__device__ __forceinline__ uint32_t smem_u32(const void* p) {
    uint32_t a;
    asm("{ .reg .u64 t; cvta.to.shared.u64 t, %1; cvt.u32.u64 %0, t; }"
        : "=r"(a) : "l"(p));
    return a;
}

__device__ __forceinline__ void ldsm4(uint32_t* r, uint32_t addr) {
    asm volatile("ldmatrix.sync.aligned.m8n8.x4.shared.b16 {%0,%1,%2,%3}, [%4];"
        : "=r"(r[0]), "=r"(r[1]), "=r"(r[2]), "=r"(r[3]) : "r"(addr));
}

__device__ __forceinline__ void mma_bf16(float* c, const uint32_t* a,
                                         uint32_t b0, uint32_t b1) {
    asm volatile(
        "mma.sync.aligned.m16n8k16.row.col.f32.bf16.bf16.f32 "
        "{%0,%1,%2,%3}, {%4,%5,%6,%7}, {%8,%9}, {%0,%1,%2,%3};\n"
        : "+f"(c[0]), "+f"(c[1]), "+f"(c[2]), "+f"(c[3])
        : "r"(a[0]), "r"(a[1]), "r"(a[2]), "r"(a[3]), "r"(b0), "r"(b1));
}

// ---------------------------------------------------------------------------
// Kernel 1: token projection. Grid (4, 32), 512 threads.
// ---------------------------------------------------------------------------
__global__ void __launch_bounds__(512) token_proj(
    const float* __restrict__ token,
    const float* __restrict__ ln1_g,
    const float* __restrict__ ln1_b,
    const float* __restrict__ w_tok,
    const float* __restrict__ b_tok)
{
    __shared__ float st[768];
    __shared__ float sred[16];
    __shared__ float sredq[16];
    __shared__ float spart[16][33];

    const int b = blockIdx.y, nq = blockIdx.x;
    const int tid = threadIdx.x;
    const int wid = tid >> 5, lane = tid & 31;
    const float* trow = token + b * 768;

    float s = 0.f, sq = 0.f;
    for (int i = tid; i < 768; i += 512) {
        float v = trow[i];
        st[i] = v;
        s += v; sq += v * v;
    }
    #pragma unroll
    for (int o = 16; o; o >>= 1) {
        s  += __shfl_down_sync(FULL, s,  o);
        sq += __shfl_down_sync(FULL, sq, o);
    }
    if (lane == 0) { sred[wid] = s; sredq[wid] = sq; }
    __syncthreads();
    if (tid == 0) {
        float ts = 0.f, tq = 0.f;
        #pragma unroll
        for (int i = 0; i < 16; i++) { ts += sred[i]; tq += sredq[i]; }
        sred[0] = ts; sredq[0] = tq;
    }
    __syncthreads();
    const float mean = sred[0] * (1.0f / 768.0f);
    const float var  = sredq[0] * (1.0f / 768.0f) - mean * mean;
    const float rstd = rsqrtf(var + 1e-6f);
    for (int i = tid; i < 768; i += 512)
        st[i] = (st[i] - mean) * rstd * ln1_g[i] + ln1_b[i];
    __syncthreads();

    const int col = nq * 32 + lane;
    const int ks = wid;
    float acc = 0.f;
    const float* sp = st + ks * 48;
    const float* wp = w_tok + (size_t)(ks * 48) * 128 + col;
    #pragma unroll
    for (int kk = 0; kk < 48; kk++)
        acc += sp[kk] * wp[(size_t)kk * 128];
    spart[ks][lane] = acc;
    __syncthreads();

    if (tid < 32) {
        float z = b_tok[nq * 32 + tid];
        #pragma unroll
        for (int i = 0; i < 16; i++) z += spart[i][tid];
        g_y[b * 128 + nq * 32 + tid] = gelu_exact(z);
    }
}

// ---------------------------------------------------------------------------
// Kernel 2: persistent fused main. 512 thr = 2 independent groups of 8 warps.
// Each group: its own stream of 32-row tiles, own A planes + stats, own named
// barrier. Shared: B planes (read-only), const params. Groups phase-shift so
// one group's GEMM overlaps the other's memory phases.
// Warp tile 16x32 (rowg=gw&1, colg=gw>>1). bf16 hi/lo 3-term GEMM.
//
// SMEM bytes:
//   [0, 51200):       A planes, group g at g*25600 (hi 32x400 | lo 32x400)
//   [51200, 153600):  B hi 128x400 | B lo 128x400
//   [153600, 157312): shared floats (SBX/SG2/SB2/SG3/SB3/INVNY)
//   [157312, 162432): per-group floats (640 words each)
// ---------------------------------------------------------------------------
#define A_STRIDE 400
#define A_PLANE  12800
#define A_GROUP  25600
#define OFF_B    51200
#define B_PLANE  51200
#define OFF_SH   153600
#define SH_SBX   0
#define SH_SG2   128
#define SH_SB2   320
#define SH_SG3   512
#define SH_SB3   704
#define SH_INVNY 896
#define OFF_GF   157312
#define GF_STRIDE 2560
#define GF_STN   0
#define GF_SMEAN 128     // [2][32]
#define GF_SVAR  192     // [2][32]
#define GF_SC    256     // [32]
#define GF_SDOT  288     // [4][32]
#define GF_SSQ   416     // [4][32]
#define SMEM_BYTES (OFF_GF + 2 * GF_STRIDE)
#define NT32 4096

__global__ void __launch_bounds__(512, 1) main_kernel(
    const float* __restrict__ x,
    const float* __restrict__ p,
    const float* __restrict__ alpha,
    const float* __restrict__ ln2_g, const float* __restrict__ ln2_b,
    const float* __restrict__ w_x,  const float* __restrict__ b_x,
    const float* __restrict__ ln3_g, const float* __restrict__ ln3_b,
    float* __restrict__ out)
{
    extern __shared__ char smc[];
    const uint32_t sbase = smem_u32(smc);
    float* sh = (float*)(smc + OFF_SH);

    const int tid = threadIdx.x;
    const int wid = tid >> 5, lane = tid & 31;
    const int grp = wid >> 3, gw = wid & 7, gtid = tid & 255;
    const int g = lane >> 2, t4 = lane & 3;
    const int rowg = gw & 1, colg = gw >> 1;
    float* gf = (float*)(smc + OFF_GF + grp * GF_STRIDE);

    // ---- shared setup (full block) ----
    if (tid < 128) sh[SH_SBX + tid] = b_x[tid];
    if (tid < 192) {
        sh[SH_SG2 + tid] = ln2_g[tid]; sh[SH_SB2 + tid] = ln2_b[tid];
        sh[SH_SG3 + tid] = ln3_g[tid]; sh[SH_SB3 + tid] = ln3_b[tid];
    }
    {   // B[n][k] = w_x[k][n], split bf16 hi/lo planes
        for (int i = tid; i < 192 * 128; i += 512) {
            const int k = i >> 7, n = i & 127;
            const float vv = w_x[i];
            __nv_bfloat16 h = __float2bfloat16(vv);
            __nv_bfloat16 l = __float2bfloat16(vv - __bfloat162float(h));
            *(__nv_bfloat16*)(smc + OFF_B + n * A_STRIDE + k * 2) = h;
            *(__nv_bfloat16*)(smc + OFF_B + B_PLANE + n * A_STRIDE + k * 2) = l;
        }
    }
    {   // 1/max(||y||,eps) per batch
        const int bb = wid * 2 + (lane >> 4);
        const int l16 = lane & 15;
        float q = 0.f;
        #pragma unroll
        for (int jj = 0; jj < 8; jj++) {
            const float v = g_y[bb * 128 + l16 + jj * 16];
            q += v * v;
        }
        #pragma unroll
        for (int o = 8; o; o >>= 1) q += __shfl_down_sync(FULL, q, o, 16);
        if (l16 == 0) sh[SH_INVNY + bb] = 1.0f / fmaxf(sqrtf(q), 1e-12f);
    }
    __syncthreads();   // last full-block barrier; groups now independent

    #define GBAR() asm volatile("bar.sync %0, 256;" :: "r"(grp + 1) : "memory")

    // ldmatrix addresses (tile-invariant)
    const uint32_t aHiA = sbase + grp * A_GROUP
        + (uint32_t)((rowg * 16 + (lane & 15)) * A_STRIDE + (lane >> 4) * 16);
    const uint32_t aLoA = aHiA + A_PLANE;
    const uint32_t bA0 = sbase + OFF_B
        + (uint32_t)((colg * 32 + (lane & 7) + ((lane >> 4) & 1) * 8) * A_STRIDE
                     + ((lane >> 3) & 1) * 16);
    const uint32_t bA1 = bA0 + 16 * A_STRIDE;

    const int step = gridDim.x * 2;
    const int t0 = blockIdx.x * 2 + grp;

    // ---- prologue prefetch of first tile ----
    float2 v[4][3], vn[4][3];
    {
        const float2* xr = (const float2*)(x + ((size_t)t0 * 32 + gw * 4) * 192);
        #pragma unroll
        for (int rr = 0; rr < 4; rr++)
            #pragma unroll
            for (int j = 0; j < 3; j++)
                v[rr][j] = xr[rr * 96 + lane + 32 * j];
    }

    int it = 0;
    for (int t = t0; t < NT32; t += step, it++) {
        const int db = (it & 1) * 32;
        const int b = t >> 7;
        const size_t base = (size_t)t * 32 * 192;

        if (gtid < 128) gf[GF_STN + gtid] = g_y[b * 128 + gtid];

        // ---- Phase 1: LN2 + bf16 hi/lo planes from registers ----
        char* AhiP = smc + grp * A_GROUP;
        char* AloP = AhiP + A_PLANE;
        #pragma unroll
        for (int rr = 0; rr < 4; rr++) {
            const int r = gw * 4 + rr;
            float s = 0.f, sq = 0.f;
            #pragma unroll
            for (int j = 0; j < 3; j++) {
                s += v[rr][j].x + v[rr][j].y;
                sq += v[rr][j].x * v[rr][j].x + v[rr][j].y * v[rr][j].y;
            }
            #pragma unroll
            for (int o = 16; o; o >>= 1) {
                s  += __shfl_down_sync(FULL, s,  o);
                sq += __shfl_down_sync(FULL, sq, o);
            }
            s  = __shfl_sync(FULL, s, 0);
            sq = __shfl_sync(FULL, sq, 0);
            const float mean = s * (1.0f / 192.0f);
            const float var  = sq * (1.0f / 192.0f) - mean * mean;
            const float rstd = rsqrtf(var + 1e-6f);
            if (lane == 0) { gf[GF_SMEAN + db + r] = mean; gf[GF_SVAR + db + r] = var; }
            #pragma unroll
            for (int j = 0; j < 3; j++) {
                const int c = 2 * lane + 64 * j;
                const float a0 = (v[rr][j].x - mean) * rstd * sh[SH_SG2 + c]     + sh[SH_SB2 + c];
                const float a1 = (v[rr][j].y - mean) * rstd * sh[SH_SG2 + c + 1] + sh[SH_SB2 + c + 1];
                __nv_bfloat162 h2 = __floats2bfloat162_rn(a0, a1);
                __nv_bfloat162 l2 = __floats2bfloat162_rn(a0 - __low2float(h2),
                                                          a1 - __high2float(h2));
                const int off = r * A_STRIDE + 4 * lane + 128 * j;
                *(uint32_t*)(AhiP + off) = *(uint32_t*)&h2;
                *(uint32_t*)(AloP + off) = *(uint32_t*)&l2;
            }
        }
        GBAR();

        // ---- prefetch next tile's x (covered by GEMM) ----
        {
            int nxt = t + step;
            if (nxt >= NT32) nxt = t;
            const float2* xr = (const float2*)(x + ((size_t)nxt * 32 + gw * 4) * 192);
            #pragma unroll
            for (int rr = 0; rr < 4; rr++)
                #pragma unroll
                for (int j = 0; j < 3; j++)
                    vn[rr][j] = xr[rr * 96 + lane + 32 * j];
        }

        // ---- Phase 2: GEMM warp tile 16x32, 12 k16-steps, 3 terms ----
        float acc[4][4];
        #pragma unroll
        for (int nt = 0; nt < 4; nt++)
            #pragma unroll
            for (int i = 0; i < 4; i++) acc[nt][i] = 0.f;

        #pragma unroll
        for (int ks = 0; ks < 12; ks++) {
            const uint32_t kb = ks * 32;
            uint32_t aH[4], aL[4], bH0[4], bH1[4], bL0[4], bL1[4];
            ldsm4(aH,  aHiA + kb);
            ldsm4(bH0, bA0 + kb);
            ldsm4(bH1, bA1 + kb);
            ldsm4(aL,  aLoA + kb);
            ldsm4(bL0, bA0 + B_PLANE + kb);
            ldsm4(bL1, bA1 + B_PLANE + kb);
            mma_bf16(acc[0], aH, bH0[0], bH0[1]);
            mma_bf16(acc[1], aH, bH0[2], bH0[3]);
            mma_bf16(acc[2], aH, bH1[0], bH1[1]);
            mma_bf16(acc[3], aH, bH1[2], bH1[3]);
            mma_bf16(acc[0], aH, bL0[0], bL0[1]);
            mma_bf16(acc[1], aH, bL0[2], bL0[3]);
            mma_bf16(acc[2], aH, bL1[0], bL1[1]);
            mma_bf16(acc[3], aH, bL1[2], bL1[3]);
            mma_bf16(acc[0], aL, bH0[0], bH0[1]);
            mma_bf16(acc[1], aL, bH0[2], bH0[3]);
            mma_bf16(acc[2], aL, bH1[0], bH1[1]);
            mma_bf16(acc[3], aL, bH1[2], bH1[3]);
        }

        // ---- Epilogue: gelu, dot(.,y)/ssq partials per colg ----
        #pragma unroll
        for (int h = 0; h < 2; h++) {
            float dot = 0.f, ssq = 0.f;
            #pragma unroll
            for (int nt = 0; nt < 4; nt++) {
                #pragma unroll
                for (int c2 = 0; c2 < 2; c2++) {
                    const int col = colg * 32 + nt * 8 + t4 * 2 + c2;
                    const float z = acc[nt][h * 2 + c2] + sh[SH_SBX + col];
                    const float e = gelu_exact(z);
                    dot += e * gf[GF_STN + col];
                    ssq += e * e;
                }
            }
            dot += __shfl_xor_sync(FULL, dot, 1);
            dot += __shfl_xor_sync(FULL, dot, 2);
            ssq += __shfl_xor_sync(FULL, ssq, 1);
            ssq += __shfl_xor_sync(FULL, ssq, 2);
            if (t4 == 0) {
                const int row = rowg * 16 + h * 8 + g;
                gf[GF_SDOT + colg * 32 + row] = dot;
                gf[GF_SSQ  + colg * 32 + row] = ssq;
            }
        }
        GBAR();

        if (gtid < 32) {
            float dot = 0.f, ssq = 0.f;
            #pragma unroll
            for (int c = 0; c < 4; c++) {
                dot += gf[GF_SDOT + c * 32 + gtid];
                ssq += gf[GF_SSQ  + c * 32 + gtid];
            }
            const float ps = p[b] * expf(alpha[0]) * sh[SH_INVNY + b];
            const float a  = ps * dot / fmaxf(sqrtf(ssq), 1e-12f);
            // LN3(a*x) = (x - m) * a * rsqrt(a^2 v + eps) * g3 + b3
            gf[GF_SC + gtid] = a * rsqrtf(a * a * gf[GF_SVAR + db + gtid] + 1e-6f);
        }
        GBAR();

        // ---- Phase 3: residual write from registers ----
        {
            float* ob = out + base;
            #pragma unroll
            for (int rr = 0; rr < 4; rr++) {
                const int r = gw * 4 + rr;
                const float m = gf[GF_SMEAN + db + r], scv = gf[GF_SC + r];
                #pragma unroll
                for (int j = 0; j < 3; j++) {
                    const int c = 2 * lane + 64 * j;
                    const float2 xv = v[rr][j];
                    float2 o;
                    o.x = 0.5f * xv.x + (xv.x - m) * scv * sh[SH_SG3 + c]     + sh[SH_SB3 + c];
                    o.y = 0.5f * xv.y + (xv.y - m) * scv * sh[SH_SG3 + c + 1] + sh[SH_SB3 + c + 1];
                    *(float2*)&ob[r * 192 + c] = o;
                }
            }
        }
        // rotate prefetched tile into current
        #pragma unroll
        for (int rr = 0; rr < 4; rr++)
            #pragma unroll
            for (int j = 0; j < 3; j++)
                v[rr][j] = vn[rr][j];
        // no barrier: phase1(i+1) plane writes are safe (GEMM(i) two barriers back),
        // smean/svar double-buffered by db.
    }
    #undef GBAR
}

// ---------------------------------------------------------------------------
extern "C" void kernel_launch(void* const* d_in, const int* in_sizes, int n_in,
                              void* d_out, int out_size)
{
    (void)in_sizes; (void)n_in; (void)out_size;
    const float* x     = (const float*)d_in[0];
    const float* token = (const float*)d_in[1];
    const float* p     = (const float*)d_in[2];
    const float* alpha = (const float*)d_in[3];
    const float* ln1_g = (const float*)d_in[4];
    const float* ln1_b = (const float*)d_in[5];
    const float* w_tok = (const float*)d_in[6];
    const float* b_tok = (const float*)d_in[7];
    const float* ln2_g = (const float*)d_in[8];
    const float* ln2_b = (const float*)d_in[9];
    const float* w_x   = (const float*)d_in[10];
    const float* b_x   = (const float*)d_in[11];
    const float* ln3_g = (const float*)d_in[12];
    const float* ln3_b = (const float*)d_in[13];
    float* out = (float*)d_out;

    token_proj<<<dim3(4, 32), 512>>>(token, ln1_g, ln1_b, w_tok, b_tok);

    static int nsm = 0;
    if (nsm == 0) {
        cudaDeviceGetAttribute(&nsm, cudaDevAttrMultiProcessorCount, 0);
        if (nsm <= 0) nsm = 148;
    }
    cudaFuncSetAttribute(main_kernel, cudaFuncAttributeMaxDynamicSharedMemorySize,
                         SMEM_BYTES);
    main_kernel<<<nsm, 512, SMEM_BYTES>>>(x, p, alpha, ln2_g, ln2_b, w_x, b_x,
                                          ln3_g, ln3_b, out);
}

// round 11
// speedup vs baseline: 2.0825x; 1.0168x over previous
#include <cuda_runtime.h>
#include <cuda_bf16.h>
#include <math.h>
#include <stdint.h>

#define FULL 0xffffffffu

__device__ float g_y[32 * 128];   // gelu(LN1(token) @ w_tok + b_tok), unnormalized

__device__ __forceinline__ float gelu_exact(float z) {
    return 0.5f * z * (1.0f + erff(z * 0.70710678118654752f));
}

__device__ __forceinline__ uint32_t smem_u32(const void* p) {
    uint32_t a;
    asm("{ .reg .u64 t; cvta.to.shared.u64 t, %1; cvt.u32.u64 %0, t; }"
        : "=r"(a) : "l"(p));
    return a;
}

__device__ __forceinline__ void ldsm4(uint32_t* r, uint32_t addr) {
    asm volatile("ldmatrix.sync.aligned.m8n8.x4.shared.b16 {%0,%1,%2,%3}, [%4];"
        : "=r"(r[0]), "=r"(r[1]), "=r"(r[2]), "=r"(r[3]) : "r"(addr));
}

__device__ __forceinline__ void mma_bf16(float* c, const uint32_t* a,
                                         uint32_t b0, uint32_t b1) {
    asm volatile(
        "mma.sync.aligned.m16n8k16.row.col.f32.bf16.bf16.f32 "
        "{%0,%1,%2,%3}, {%4,%5,%6,%7}, {%8,%9}, {%0,%1,%2,%3};\n"
        : "+f"(c[0]), "+f"(c[1]), "+f"(c[2]), "+f"(c[3])
        : "r"(a[0]), "r"(a[1]), "r"(a[2]), "r"(a[3]), "r"(b0), "r"(b1));
}

// ---------------------------------------------------------------------------
// Kernel 1: token projection. Grid (4, 32), 512 threads.
// ---------------------------------------------------------------------------
__global__ void __launch_bounds__(512) token_proj(
    const float* __restrict__ token,
    const float* __restrict__ ln1_g,
    const float* __restrict__ ln1_b,
    const float* __restrict__ w_tok,
    const float* __restrict__ b_tok)
{
    __shared__ float st[768];
    __shared__ float sred[16];
    __shared__ float sredq[16];
    __shared__ float spart[16][33];

    const int b = blockIdx.y, nq = blockIdx.x;
    const int tid = threadIdx.x;
    const int wid = tid >> 5, lane = tid & 31;
    const float* trow = token + b * 768;

    float s = 0.f, sq = 0.f;
    for (int i = tid; i < 768; i += 512) {
        float v = trow[i];
        st[i] = v;
        s += v; sq += v * v;
    }
    #pragma unroll
    for (int o = 16; o; o >>= 1) {
        s  += __shfl_down_sync(FULL, s,  o);
        sq += __shfl_down_sync(FULL, sq, o);
    }
    if (lane == 0) { sred[wid] = s; sredq[wid] = sq; }
    __syncthreads();
    if (tid == 0) {
        float ts = 0.f, tq = 0.f;
        #pragma unroll
        for (int i = 0; i < 16; i++) { ts += sred[i]; tq += sredq[i]; }
        sred[0] = ts; sredq[0] = tq;
    }
    __syncthreads();
    const float mean = sred[0] * (1.0f / 768.0f);
    const float var  = sredq[0] * (1.0f / 768.0f) - mean * mean;
    const float rstd = rsqrtf(var + 1e-6f);
    for (int i = tid; i < 768; i += 512)
        st[i] = (st[i] - mean) * rstd * ln1_g[i] + ln1_b[i];
    __syncthreads();

    const int col = nq * 32 + lane;
    const int ks = wid;
    float acc = 0.f;
    const float* sp = st + ks * 48;
    const float* wp = w_tok + (size_t)(ks * 48) * 128 + col;
    #pragma unroll
    for (int kk = 0; kk < 48; kk++)
        acc += sp[kk] * wp[(size_t)kk * 128];
    spart[ks][lane] = acc;
    __syncthreads();

    if (tid < 32) {
        float z = b_tok[nq * 32 + tid];
        #pragma unroll
        for (int i = 0; i < 16; i++) z += spart[i][tid];
        g_y[b * 128 + nq * 32 + tid] = gelu_exact(z);
    }
}

// ---------------------------------------------------------------------------
// Kernel 2: persistent fused main. 512 thr = 2 independent 8-warp groups,
// each with its own 32-row tile stream, A planes, stats, named barrier.
// 2 barriers per tile; scale computed per-warp (no serial section).
// Warp tile 16x32 (rowg=gw&1, colg=gw>>1). bf16 hi/lo 3-term GEMM, ldmatrix.
//
// SMEM bytes:
//   [0, 51200):       A planes, group g at g*25600 (hi 32x400 | lo 32x400)
//   [51200, 153600):  B hi 128x400 | B lo 128x400
//   [153600, +800w):  shared floats (SG2/SB2/SG3/SB3/INVNY)
//   then per-group floats (384 words each)
// ---------------------------------------------------------------------------
#define A_STRIDE 400
#define A_PLANE  12800
#define A_GROUP  25600
#define OFF_B    51200
#define B_PLANE  51200
#define OFF_SH   153600
#define SH_SG2   0
#define SH_SB2   192
#define SH_SG3   384
#define SH_SB3   576
#define SH_INVNY 768
#define SH_WORDS 800
#define OFF_GF   (OFF_SH + SH_WORDS * 4)
#define GF_STRIDE 1536
#define GF_SMEAN 0       // [2][32]
#define GF_SVAR  64      // [2][32]
#define GF_SDOT  128     // [4][32]
#define GF_SSQ   256     // [4][32]
#define SMEM_BYTES (OFF_GF + 2 * GF_STRIDE)
#define NT32 4096

__global__ void __launch_bounds__(512, 1) main_kernel(
    const float* __restrict__ x,
    const float* __restrict__ p,
    const float* __restrict__ alpha,
    const float* __restrict__ ln2_g, const float* __restrict__ ln2_b,
    const float* __restrict__ w_x,  const float* __restrict__ b_x,
    const float* __restrict__ ln3_g, const float* __restrict__ ln3_b,
    float* __restrict__ out)
{
    extern __shared__ char smc[];
    const uint32_t sbase = smem_u32(smc);
    float* sh = (float*)(smc + OFF_SH);

    const int tid = threadIdx.x;
    const int wid = tid >> 5, lane = tid & 31;
    const int grp = wid >> 3, gw = wid & 7;
    const int g = lane >> 2, t4 = lane & 3;
    const int rowg = gw & 1, colg = gw >> 1;
    float* gf = (float*)(smc + OFF_GF + grp * GF_STRIDE);

    // ---- shared setup (full block) ----
    if (tid < 192) {
        sh[SH_SG2 + tid] = ln2_g[tid]; sh[SH_SB2 + tid] = ln2_b[tid];
        sh[SH_SG3 + tid] = ln3_g[tid]; sh[SH_SB3 + tid] = ln3_b[tid];
    }
    {   // B[n][k] = w_x[k][n], split bf16 hi/lo planes
        for (int i = tid; i < 192 * 128; i += 512) {
            const int k = i >> 7, n = i & 127;
            const float vv = w_x[i];
            __nv_bfloat16 h = __float2bfloat16(vv);
            __nv_bfloat16 l = __float2bfloat16(vv - __bfloat162float(h));
            *(__nv_bfloat16*)(smc + OFF_B + n * A_STRIDE + k * 2) = h;
            *(__nv_bfloat16*)(smc + OFF_B + B_PLANE + n * A_STRIDE + k * 2) = l;
        }
    }
    {   // 1/max(||y||,eps) per batch
        const int bb = wid * 2 + (lane >> 4);
        const int l16 = lane & 15;
        float q = 0.f;
        #pragma unroll
        for (int jj = 0; jj < 8; jj++) {
            const float v = g_y[bb * 128 + l16 + jj * 16];
            q += v * v;
        }
        #pragma unroll
        for (int o = 8; o; o >>= 1) q += __shfl_down_sync(FULL, q, o, 16);
        if (l16 == 0) sh[SH_INVNY + bb] = 1.0f / fmaxf(sqrtf(q), 1e-12f);
    }
    // per-thread constants: bias for the 8 epilogue columns, exp(alpha)
    const float expAlpha = expf(alpha[0]);
    float2 bx[4];
    #pragma unroll
    for (int nt = 0; nt < 4; nt++)
        bx[nt] = *(const float2*)&b_x[colg * 32 + nt * 8 + t4 * 2];
    __syncthreads();   // last full-block barrier; groups now independent

    #define GBAR() asm volatile("bar.sync %0, 256;" :: "r"(grp + 1) : "memory")

    // ldmatrix addresses (tile-invariant)
    const uint32_t aHiA = sbase + grp * A_GROUP
        + (uint32_t)((rowg * 16 + (lane & 15)) * A_STRIDE + (lane >> 4) * 16);
    const uint32_t aLoA = aHiA + A_PLANE;
    const uint32_t bA0 = sbase + OFF_B
        + (uint32_t)((colg * 32 + (lane & 7) + ((lane >> 4) & 1) * 8) * A_STRIDE
                     + ((lane >> 3) & 1) * 16);
    const uint32_t bA1 = bA0 + 16 * A_STRIDE;

    const int step = gridDim.x * 2;
    const int t0 = blockIdx.x * 2 + grp;

    // ---- prologue prefetch of first tile ----
    float2 v[4][3], vn[4][3];
    {
        const float2* xr = (const float2*)(x + ((size_t)t0 * 32 + gw * 4) * 192);
        #pragma unroll
        for (int rr = 0; rr < 4; rr++)
            #pragma unroll
            for (int j = 0; j < 3; j++)
                v[rr][j] = xr[rr * 96 + lane + 32 * j];
    }

    int it = 0;
    for (int t = t0; t < NT32; t += step, it++) {
        const int db = (it & 1) * 32;
        const int b = t >> 7;
        const size_t base = (size_t)t * 32 * 192;

        // ---- early prefetch: next-tile x, this-tile tn cols, p[b] ----
        {
            int nxt = t + step;
            if (nxt >= NT32) nxt = t;
            const float2* xr = (const float2*)(x + ((size_t)nxt * 32 + gw * 4) * 192);
            #pragma unroll
            for (int rr = 0; rr < 4; rr++)
                #pragma unroll
                for (int j = 0; j < 3; j++)
                    vn[rr][j] = xr[rr * 96 + lane + 32 * j];
        }
        float2 stn[4];
        #pragma unroll
        for (int nt = 0; nt < 4; nt++)
            stn[nt] = *(const float2*)&g_y[b * 128 + colg * 32 + nt * 8 + t4 * 2];
        const float pb = p[b];

        // ---- Phase 1: LN2 + bf16 hi/lo planes from registers ----
        char* AhiP = smc + grp * A_GROUP;
        char* AloP = AhiP + A_PLANE;
        #pragma unroll
        for (int rr = 0; rr < 4; rr++) {
            const int r = gw * 4 + rr;
            float s = 0.f, sq = 0.f;
            #pragma unroll
            for (int j = 0; j < 3; j++) {
                s += v[rr][j].x + v[rr][j].y;
                sq += v[rr][j].x * v[rr][j].x + v[rr][j].y * v[rr][j].y;
            }
            #pragma unroll
            for (int o = 16; o; o >>= 1) {
                s  += __shfl_xor_sync(FULL, s,  o);
                sq += __shfl_xor_sync(FULL, sq, o);
            }
            const float mean = s * (1.0f / 192.0f);
            const float var  = sq * (1.0f / 192.0f) - mean * mean;
            const float rstd = rsqrtf(var + 1e-6f);
            if (lane == 0) { gf[GF_SMEAN + db + r] = mean; gf[GF_SVAR + db + r] = var; }
            #pragma unroll
            for (int j = 0; j < 3; j++) {
                const int c = 2 * lane + 64 * j;
                const float a0 = (v[rr][j].x - mean) * rstd * sh[SH_SG2 + c]     + sh[SH_SB2 + c];
                const float a1 = (v[rr][j].y - mean) * rstd * sh[SH_SG2 + c + 1] + sh[SH_SB2 + c + 1];
                __nv_bfloat162 h2 = __floats2bfloat162_rn(a0, a1);
                __nv_bfloat162 l2 = __floats2bfloat162_rn(a0 - __low2float(h2),
                                                          a1 - __high2float(h2));
                const int off = r * A_STRIDE + 4 * lane + 128 * j;
                *(uint32_t*)(AhiP + off) = *(uint32_t*)&h2;
                *(uint32_t*)(AloP + off) = *(uint32_t*)&l2;
            }
        }
        GBAR();

        // ---- Phase 2: GEMM warp tile 16x32, 12 k16-steps, 3 terms ----
        float acc[4][4];
        #pragma unroll
        for (int nt = 0; nt < 4; nt++)
            #pragma unroll
            for (int i = 0; i < 4; i++) acc[nt][i] = 0.f;

        #pragma unroll
        for (int ks = 0; ks < 12; ks++) {
            const uint32_t kb = ks * 32;
            uint32_t aH[4], aL[4], bH0[4], bH1[4], bL0[4], bL1[4];
            ldsm4(aH,  aHiA + kb);
            ldsm4(bH0, bA0 + kb);
            ldsm4(bH1, bA1 + kb);
            ldsm4(aL,  aLoA + kb);
            ldsm4(bL0, bA0 + B_PLANE + kb);
            ldsm4(bL1, bA1 + B_PLANE + kb);
            mma_bf16(acc[0], aH, bH0[0], bH0[1]);
            mma_bf16(acc[1], aH, bH0[2], bH0[3]);
            mma_bf16(acc[2], aH, bH1[0], bH1[1]);
            mma_bf16(acc[3], aH, bH1[2], bH1[3]);
            mma_bf16(acc[0], aH, bL0[0], bL0[1]);
            mma_bf16(acc[1], aH, bL0[2], bL0[3]);
            mma_bf16(acc[2], aH, bL1[0], bL1[1]);
            mma_bf16(acc[3], aH, bL1[2], bL1[3]);
            mma_bf16(acc[0], aL, bH0[0], bH0[1]);
            mma_bf16(acc[1], aL, bH0[2], bH0[3]);
            mma_bf16(acc[2], aL, bH1[0], bH1[1]);
            mma_bf16(acc[3], aL, bH1[2], bH1[3]);
        }

        // ---- Epilogue: gelu, dot(.,y)/ssq partials per colg ----
        #pragma unroll
        for (int h = 0; h < 2; h++) {
            float dot = 0.f, ssq = 0.f;
            #pragma unroll
            for (int nt = 0; nt < 4; nt++) {
                #pragma unroll
                for (int c2 = 0; c2 < 2; c2++) {
                    const float z = acc[nt][h * 2 + c2]
                                  + (c2 ? bx[nt].y : bx[nt].x);
                    const float e = gelu_exact(z);
                    dot += e * (c2 ? stn[nt].y : stn[nt].x);
                    ssq += e * e;
                }
            }
            dot += __shfl_xor_sync(FULL, dot, 1);
            dot += __shfl_xor_sync(FULL, dot, 2);
            ssq += __shfl_xor_sync(FULL, ssq, 1);
            ssq += __shfl_xor_sync(FULL, ssq, 2);
            if (t4 == 0) {
                const int row = rowg * 16 + h * 8 + g;
                gf[GF_SDOT + colg * 32 + row] = dot;
                gf[GF_SSQ  + colg * 32 + row] = ssq;
            }
        }
        GBAR();

        // ---- per-warp scale for this warp's 4 phase-3 rows ----
        float myMean, mySc;
        {
            const int row = gw * 4 + (lane & 3);
            float dot = 0.f, ssq = 0.f;
            #pragma unroll
            for (int c = 0; c < 4; c++) {
                dot += gf[GF_SDOT + c * 32 + row];
                ssq += gf[GF_SSQ  + c * 32 + row];
            }
            const float ps = pb * expAlpha * sh[SH_INVNY + b];
            const float a  = ps * dot / fmaxf(sqrtf(ssq), 1e-12f);
            // LN3(a*x) = (x - m) * a * rsqrt(a^2 v + eps) * g3 + b3
            mySc = a * rsqrtf(a * a * gf[GF_SVAR + db + row] + 1e-6f);
            myMean = gf[GF_SMEAN + db + row];
        }

        // ---- Phase 3: residual write from registers ----
        {
            float* ob = out + base;
            #pragma unroll
            for (int rr = 0; rr < 4; rr++) {
                const int r = gw * 4 + rr;
                const float m   = __shfl_sync(FULL, myMean, rr);
                const float scv = __shfl_sync(FULL, mySc, rr);
                #pragma unroll
                for (int j = 0; j < 3; j++) {
                    const int c = 2 * lane + 64 * j;
                    const float2 xv = v[rr][j];
                    float2 o;
                    o.x = 0.5f * xv.x + (xv.x - m) * scv * sh[SH_SG3 + c]     + sh[SH_SB3 + c];
                    o.y = 0.5f * xv.y + (xv.y - m) * scv * sh[SH_SG3 + c + 1] + sh[SH_SB3 + c + 1];
                    *(float2*)&ob[r * 192 + c] = o;
                }
            }
        }
        // rotate prefetched tile into current
        #pragma unroll
        for (int rr = 0; rr < 4; rr++)
            #pragma unroll
            for (int j = 0; j < 3; j++)
                v[rr][j] = vn[rr][j];
        // no barrier: phase1(i+1) A-writes are safe (all warps passed the
        // post-epilogue barrier, so GEMM(i) reads are complete); smean/svar
        // and partials are protected by the two barriers + db double-buffer.
    }
    #undef GBAR
}

// ---------------------------------------------------------------------------
extern "C" void kernel_launch(void* const* d_in, const int* in_sizes, int n_in,
                              void* d_out, int out_size)
{
    (void)in_sizes; (void)n_in; (void)out_size;
    const float* x     = (const float*)d_in[0];
    const float* token = (const float*)d_in[1];
    const float* p     = (const float*)d_in[2];
    const float* alpha = (const float*)d_in[3];
    const float* ln1_g = (const float*)d_in[4];
    const float* ln1_b = (const float*)d_in[5];
    const float* w_tok = (const float*)d_in[6];
    const float* b_tok = (const float*)d_in[7];
    const float* ln2_g = (const float*)d_in[8];
    const float* ln2_b = (const float*)d_in[9];
    const float* w_x   = (const float*)d_in[10];
    const float* b_x   = (const float*)d_in[11];
    const float* ln3_g = (const float*)d_in[12];
    const float* ln3_b = (const float*)d_in[13];
    float* out = (float*)d_out;

    token_proj<<<dim3(4, 32), 512>>>(token, ln1_g, ln1_b, w_tok, b_tok);

    static int nsm = 0;
    if (nsm == 0) {
        cudaDeviceGetAttribute(&nsm, cudaDevAttrMultiProcessorCount, 0);
        if (nsm <= 0) nsm = 148;
    }
    cudaFuncSetAttribute(main_kernel, cudaFuncAttributeMaxDynamicSharedMemorySize,
                         SMEM_BYTES);
    main_kernel<<<nsm, 512, SMEM_BYTES>>>(x, p, alpha, ln2_g, ln2_b, w_x, b_x,
                                          ln3_g, ln3_b, out);
}